// round 1
// baseline (speedup 1.0000x reference)
#include <cuda_runtime.h>
#include <math.h>
#include <stdint.h>

#define T_TOK 8192
#define HIDDEN 2048
#define NH 16
#define NKV 4
#define HD 128
#define BATCH 8
#define SEQ 1024

// -------- scratch (device globals: no allocation allowed) --------
__device__ float g_q[(size_t)T_TOK * NH * HD];     // 64 MB
__device__ float g_k[(size_t)T_TOK * NKV * HD];    // 16 MB
__device__ float g_v[(size_t)T_TOK * NKV * HD];    // 16 MB
__device__ float g_o[(size_t)T_TOK * NH * HD];     // 64 MB
__device__ int   g_perm[T_TOK];
__device__ int   g_n0;

// =================================================================
// 1) stable partition of tokens by route (gen_mask>0)
// =================================================================
__global__ void partition_kernel(const int* __restrict__ gm) {
    __shared__ int sc[1024];
    int tid = threadIdx.x;
    int base = tid * 8;
    int z = 0;
#pragma unroll
    for (int i = 0; i < 8; i++) z += (gm[base + i] > 0) ? 0 : 1;
    sc[tid] = z;
    __syncthreads();
    // inclusive scan (Hillis-Steele)
    for (int off = 1; off < 1024; off <<= 1) {
        int v = (tid >= off) ? sc[tid - off] : 0;
        __syncthreads();
        sc[tid] += v;
        __syncthreads();
    }
    int total0 = sc[1023];
    int zpos = sc[tid] - z;     // zeros before my chunk
    int opos = base - zpos;     // ones before my chunk
#pragma unroll
    for (int i = 0; i < 8; i++) {
        int t = base + i;
        if (gm[t] > 0) g_perm[total0 + opos++] = t;
        else           g_perm[zpos++] = t;
    }
    if (tid == 0) g_n0 = total0;
}

// =================================================================
// 2) routed SGEMM:  C[perm[r], c] = X[perm[r], :] @ Wsel[c, :]^T + bsel[c]
//    BM=BN=128, BK=8, 256 threads, 8x8 microtile. K fixed = 2048.
// =================================================================
__global__ __launch_bounds__(256)
void gemm_routed(const float* __restrict__ X,
                 const float* __restrict__ W0, const float* __restrict__ W1,
                 const float* __restrict__ b0, const float* __restrict__ b1,
                 float* __restrict__ C, int N) {
    __shared__ float Xs[8 * 128];
    __shared__ float Ws0[8 * 128];
    __shared__ float Ws1[8 * 128];
    __shared__ int Prm[128];

    const int tid = threadIdx.x;
    const int tx = tid & 15, ty = tid >> 4;
    const int r0 = blockIdx.y * 128, c0 = blockIdx.x * 128;
    const int n0 = g_n0;

    if (tid < 128) Prm[tid] = g_perm[r0 + tid];
    __syncthreads();

    const bool allA = (r0 + 128 <= n0);
    const bool allB = (r0 >= n0);

    float acc[8][8];
#pragma unroll
    for (int i = 0; i < 8; i++)
#pragma unroll
        for (int j = 0; j < 8; j++) acc[i][j] = 0.0f;

    const int m = tid >> 1;
    const int kq = (tid & 1) * 4;
    const size_t xrow = (size_t)Prm[m] * HIDDEN;
    const size_t wrow = (size_t)(c0 + m) * HIDDEN;

    if (allA || allB) {
        const float* __restrict__ Wu = allB ? W1 : W0;
        for (int k0 = 0; k0 < HIDDEN; k0 += 8) {
            float4 xv = *(const float4*)(X + xrow + k0 + kq);
            float4 wv = *(const float4*)(Wu + wrow + k0 + kq);
            Xs[(kq + 0) * 128 + m] = xv.x; Xs[(kq + 1) * 128 + m] = xv.y;
            Xs[(kq + 2) * 128 + m] = xv.z; Xs[(kq + 3) * 128 + m] = xv.w;
            Ws0[(kq + 0) * 128 + m] = wv.x; Ws0[(kq + 1) * 128 + m] = wv.y;
            Ws0[(kq + 2) * 128 + m] = wv.z; Ws0[(kq + 3) * 128 + m] = wv.w;
            __syncthreads();
#pragma unroll
            for (int kk = 0; kk < 8; kk++) {
                float4 xa = *(const float4*)&Xs[kk * 128 + ty * 8];
                float4 xb = *(const float4*)&Xs[kk * 128 + ty * 8 + 4];
                float4 wa = *(const float4*)&Ws0[kk * 128 + tx * 8];
                float4 wb = *(const float4*)&Ws0[kk * 128 + tx * 8 + 4];
                float xf[8] = {xa.x, xa.y, xa.z, xa.w, xb.x, xb.y, xb.z, xb.w};
                float wf[8] = {wa.x, wa.y, wa.z, wa.w, wb.x, wb.y, wb.z, wb.w};
#pragma unroll
                for (int i = 0; i < 8; i++)
#pragma unroll
                    for (int j = 0; j < 8; j++) acc[i][j] += xf[i] * wf[j];
            }
            __syncthreads();
        }
    } else {
        // boundary tile: mixed routes, per-row weight select (rare: <=1 row-block)
        bool rb[8];
#pragma unroll
        for (int i = 0; i < 8; i++) rb[i] = (r0 + ty * 8 + i) >= n0;
        for (int k0 = 0; k0 < HIDDEN; k0 += 8) {
            float4 xv = *(const float4*)(X + xrow + k0 + kq);
            float4 w0v = *(const float4*)(W0 + wrow + k0 + kq);
            float4 w1v = *(const float4*)(W1 + wrow + k0 + kq);
            Xs[(kq + 0) * 128 + m] = xv.x; Xs[(kq + 1) * 128 + m] = xv.y;
            Xs[(kq + 2) * 128 + m] = xv.z; Xs[(kq + 3) * 128 + m] = xv.w;
            Ws0[(kq + 0) * 128 + m] = w0v.x; Ws0[(kq + 1) * 128 + m] = w0v.y;
            Ws0[(kq + 2) * 128 + m] = w0v.z; Ws0[(kq + 3) * 128 + m] = w0v.w;
            Ws1[(kq + 0) * 128 + m] = w1v.x; Ws1[(kq + 1) * 128 + m] = w1v.y;
            Ws1[(kq + 2) * 128 + m] = w1v.z; Ws1[(kq + 3) * 128 + m] = w1v.w;
            __syncthreads();
#pragma unroll
            for (int kk = 0; kk < 8; kk++) {
                float xf[8], w0f[8], w1f[8];
#pragma unroll
                for (int i = 0; i < 8; i++) xf[i] = Xs[kk * 128 + ty * 8 + i];
#pragma unroll
                for (int j = 0; j < 8; j++) {
                    w0f[j] = Ws0[kk * 128 + tx * 8 + j];
                    w1f[j] = Ws1[kk * 128 + tx * 8 + j];
                }
#pragma unroll
                for (int i = 0; i < 8; i++)
#pragma unroll
                    for (int j = 0; j < 8; j++)
                        acc[i][j] += xf[i] * (rb[i] ? w1f[j] : w0f[j]);
            }
            __syncthreads();
        }
    }

#pragma unroll
    for (int i = 0; i < 8; i++) {
        int gr = r0 + ty * 8 + i;
        int tok = Prm[ty * 8 + i];
        bool rt = gr >= n0;
        const float* bb = rt ? b1 : b0;
        int cbase = c0 + tx * 8;
        float4 o0, o1;
        o0.x = acc[i][0]; o0.y = acc[i][1]; o0.z = acc[i][2]; o0.w = acc[i][3];
        o1.x = acc[i][4]; o1.y = acc[i][5]; o1.z = acc[i][6]; o1.w = acc[i][7];
        if (bb) {
            o0.x += bb[cbase + 0]; o0.y += bb[cbase + 1];
            o0.z += bb[cbase + 2]; o0.w += bb[cbase + 3];
            o1.x += bb[cbase + 4]; o1.y += bb[cbase + 5];
            o1.z += bb[cbase + 6]; o1.w += bb[cbase + 7];
        }
        float* cp = C + (size_t)tok * N + cbase;
        *(float4*)(cp) = o0;
        *(float4*)(cp + 4) = o1;
    }
}

// =================================================================
// 3) fused per-head RMS norm + RoPE (one warp per (token, head))
// =================================================================
__global__ void rmsrope_kernel(const int* __restrict__ gm,
                               const float* __restrict__ cosb,
                               const float* __restrict__ sinb,
                               const float* __restrict__ qw,
                               const float* __restrict__ qwg,
                               const float* __restrict__ kw,
                               const float* __restrict__ kwg) {
    const int warp = (blockIdx.x * blockDim.x + threadIdx.x) >> 5;
    const int lane = threadIdx.x & 31;
    const int QP = T_TOK * NH;
    const int TOTAL = QP + T_TOK * NKV;
    if (warp >= TOTAL) return;

    float* ptr;
    const float* w;
    int t;
    if (warp < QP) {
        t = warp >> 4;
        ptr = g_q + (size_t)warp * HD;
        bool rt = gm[t] > 0;
        w = rt ? qwg : qw;
    } else {
        int p = warp - QP;
        t = p >> 2;
        ptr = g_k + (size_t)p * HD;
        bool rt = gm[t] > 0;
        w = rt ? kwg : kw;
    }

    float v[4];
#pragma unroll
    for (int r = 0; r < 4; r++) v[r] = ptr[lane + 32 * r];
    float ss = v[0] * v[0] + v[1] * v[1] + v[2] * v[2] + v[3] * v[3];
#pragma unroll
    for (int off = 16; off > 0; off >>= 1)
        ss += __shfl_xor_sync(0xffffffffu, ss, off);
    float rs = rsqrtf(ss * (1.0f / 128.0f) + 1e-6f);

#pragma unroll
    for (int r = 0; r < 4; r++) {
        int d = lane + 32 * r;
        v[r] = v[r] * rs * w[d];
    }
    // rope: d<64 -> rot=-x[d+64]; d>=64 -> rot=x[d-64]
    float rot[4] = {-v[2], -v[3], v[0], v[1]};
#pragma unroll
    for (int r = 0; r < 4; r++) {
        int d = lane + 32 * r;
        float c = cosb[(size_t)t * HD + d];
        float s = sinb[(size_t)t * HD + d];
        ptr[d] = v[r] * c + rot[r] * s;
    }
}

// =================================================================
// 4) flash attention, fp32, causal, GQA (kv head = h/4)
//    grid (L/64, H, B), 256 threads, BM=BN=64, D=128
// =================================================================
#define ATT_SMEM_FLOATS (128 * 65 + 128 * 65 + 64 * 132 + 64 * 65)

__global__ __launch_bounds__(256)
void attn_kernel(const float* __restrict__ q, const float* __restrict__ k,
                 const float* __restrict__ v, float* __restrict__ o) {
    extern __shared__ float sm[];
    float* Qs = sm;                 // [d][m] stride 65
    float* Ks = Qs + 128 * 65;      // [d][n] stride 65
    float* Vs = Ks + 128 * 65;      // [n][d] stride 132
    float* Ps = Vs + 64 * 132;      // [j][i] stride 65

    const int tid = threadIdx.x;
    const int tx = tid & 15, ty = tid >> 4;
    const int qb = blockIdx.x, h = blockIdx.y, b = blockIdx.z;
    const int kvh = h >> 2;
    const float scale = 0.08838834764831845f; // 1/sqrt(128)

    // load Q transposed, pre-scaled
    for (int idx = tid; idx < 64 * 128; idx += 256) {
        int mm = idx >> 7, d = idx & 127;
        Qs[d * 65 + mm] =
            q[(((size_t)(b * SEQ + qb * 64 + mm)) * NH + h) * HD + d] * scale;
    }

    float mi[4], li[4], acc[4][8];
#pragma unroll
    for (int i = 0; i < 4; i++) {
        mi[i] = -1e30f; li[i] = 0.0f;
#pragma unroll
        for (int j = 0; j < 8; j++) acc[i][j] = 0.0f;
    }

    for (int kb = 0; kb <= qb; kb++) {
        __syncthreads();
        for (int idx = tid; idx < 64 * 128; idx += 256) {
            int n = idx >> 7, d = idx & 127;
            size_t g = (((size_t)(b * SEQ + kb * 64 + n)) * NKV + kvh) * HD + d;
            Ks[d * 65 + n] = k[g];
            Vs[n * 132 + d] = v[g];
        }
        __syncthreads();

        float s[4][4];
#pragma unroll
        for (int i = 0; i < 4; i++)
#pragma unroll
            for (int j = 0; j < 4; j++) s[i][j] = 0.0f;

#pragma unroll 4
        for (int d = 0; d < 128; d++) {
            float qf[4], kf[4];
#pragma unroll
            for (int i = 0; i < 4; i++) qf[i] = Qs[d * 65 + ty * 4 + i];
#pragma unroll
            for (int j = 0; j < 4; j++) kf[j] = Ks[d * 65 + tx * 4 + j];
#pragma unroll
            for (int i = 0; i < 4; i++)
#pragma unroll
                for (int j = 0; j < 4; j++) s[i][j] += qf[i] * kf[j];
        }

        if (kb == qb) {
#pragma unroll
            for (int i = 0; i < 4; i++)
#pragma unroll
                for (int j = 0; j < 4; j++)
                    if (tx * 4 + j > ty * 4 + i) s[i][j] = -1e30f;
        }

        // online softmax per row (16-lane reduce across tx group)
#pragma unroll
        for (int i = 0; i < 4; i++) {
            float rm = fmaxf(fmaxf(s[i][0], s[i][1]), fmaxf(s[i][2], s[i][3]));
#pragma unroll
            for (int off = 8; off > 0; off >>= 1)
                rm = fmaxf(rm, __shfl_xor_sync(0xffffffffu, rm, off));
            float mn = fmaxf(mi[i], rm);
            float corr = __expf(mi[i] - mn);
            float ps = 0.0f;
#pragma unroll
            for (int j = 0; j < 4; j++) {
                float p = __expf(s[i][j] - mn);
                s[i][j] = p;
                ps += p;
            }
#pragma unroll
            for (int off = 8; off > 0; off >>= 1)
                ps += __shfl_xor_sync(0xffffffffu, ps, off);
            li[i] = li[i] * corr + ps;
            mi[i] = mn;
#pragma unroll
            for (int j = 0; j < 8; j++) acc[i][j] *= corr;
        }

        // stage P transposed [j][i]
#pragma unroll
        for (int i = 0; i < 4; i++)
#pragma unroll
            for (int j = 0; j < 4; j++)
                Ps[(tx * 4 + j) * 65 + ty * 4 + i] = s[i][j];
        __syncthreads();

        // O += P @ V
#pragma unroll 2
        for (int j = 0; j < 64; j++) {
            float pf[4];
#pragma unroll
            for (int i = 0; i < 4; i++) pf[i] = Ps[j * 65 + ty * 4 + i];
            float4 va = *(const float4*)&Vs[j * 132 + tx * 8];
            float4 vb = *(const float4*)&Vs[j * 132 + tx * 8 + 4];
            float vf[8] = {va.x, va.y, va.z, va.w, vb.x, vb.y, vb.z, vb.w};
#pragma unroll
            for (int i = 0; i < 4; i++)
#pragma unroll
                for (int jj = 0; jj < 8; jj++) acc[i][jj] += pf[i] * vf[jj];
        }
    }

#pragma unroll
    for (int i = 0; i < 4; i++) {
        float inv = 1.0f / li[i];
        float* op = o + (((size_t)(b * SEQ + qb * 64 + ty * 4 + i)) * NH + h) * HD + tx * 8;
        float4 o0, o1;
        o0.x = acc[i][0] * inv; o0.y = acc[i][1] * inv;
        o0.z = acc[i][2] * inv; o0.w = acc[i][3] * inv;
        o1.x = acc[i][4] * inv; o1.y = acc[i][5] * inv;
        o1.z = acc[i][6] * inv; o1.w = acc[i][7] * inv;
        *(float4*)(op) = o0;
        *(float4*)(op + 4) = o1;
    }
}

// =================================================================
// launch
// =================================================================
extern "C" void kernel_launch(void* const* d_in, const int* in_sizes, int n_in,
                              void* d_out, int out_size) {
    const float* x    = (const float*)d_in[0];
    const float* cosb = (const float*)d_in[1];
    const float* sinb = (const float*)d_in[2];
    // d_in[3] = attn_bias (exactly causal 0/-1e9; applied analytically)
    const int*   gm   = (const int*)d_in[4];
    const float* Wq   = (const float*)d_in[5];
    const float* bq   = (const float*)d_in[6];
    const float* Wqg  = (const float*)d_in[7];
    const float* bqg  = (const float*)d_in[8];
    const float* Wk   = (const float*)d_in[9];
    const float* bk   = (const float*)d_in[10];
    const float* Wkg  = (const float*)d_in[11];
    const float* bkg  = (const float*)d_in[12];
    const float* Wv   = (const float*)d_in[13];
    const float* bv   = (const float*)d_in[14];
    const float* Wvg  = (const float*)d_in[15];
    const float* bvg  = (const float*)d_in[16];
    const float* Wo   = (const float*)d_in[17];
    const float* Wog  = (const float*)d_in[18];
    const float* qw   = (const float*)d_in[19];
    const float* qwg  = (const float*)d_in[20];
    const float* kw   = (const float*)d_in[21];
    const float* kwg  = (const float*)d_in[22];
    float* out = (float*)d_out;

    void *pq, *pk, *pv, *po;
    cudaGetSymbolAddress(&pq, g_q);
    cudaGetSymbolAddress(&pk, g_k);
    cudaGetSymbolAddress(&pv, g_v);
    cudaGetSymbolAddress(&po, g_o);
    float* qbuf = (float*)pq;
    float* kbuf = (float*)pk;
    float* vbuf = (float*)pv;
    float* obuf = (float*)po;

    static const size_t att_smem = ATT_SMEM_FLOATS * sizeof(float);
    cudaFuncSetAttribute(attn_kernel, cudaFuncAttributeMaxDynamicSharedMemorySize,
                         (int)att_smem);

    // 1) partition tokens by route
    partition_kernel<<<1, 1024>>>(gm);

    // 2) routed QKV projections (gathered rows via perm, 1x flops)
    gemm_routed<<<dim3(NH * HD / 128, T_TOK / 128), 256>>>(
        x, Wq, Wqg, bq, bqg, qbuf, NH * HD);
    gemm_routed<<<dim3(NKV * HD / 128, T_TOK / 128), 256>>>(
        x, Wk, Wkg, bk, bkg, kbuf, NKV * HD);
    gemm_routed<<<dim3(NKV * HD / 128, T_TOK / 128), 256>>>(
        x, Wv, Wvg, bv, bvg, vbuf, NKV * HD);

    // 3) RMS norm + RoPE (in place on qbuf/kbuf)
    {
        int warps = T_TOK * (NH + NKV);
        int blocks = (warps * 32 + 255) / 256;
        rmsrope_kernel<<<blocks, 256>>>(gm, cosb, sinb, qw, qwg, kw, kwg);
    }

    // 4) causal GQA flash attention
    attn_kernel<<<dim3(SEQ / 64, NH, BATCH), 256, att_smem>>>(
        qbuf, kbuf, vbuf, obuf);

    // 5) routed output projection -> d_out
    gemm_routed<<<dim3(HIDDEN / 128, T_TOK / 128), 256>>>(
        obuf, Wo, Wog, nullptr, nullptr, out, HIDDEN);
}

// round 2
// speedup vs baseline: 1.0027x; 1.0027x over previous
#include <cuda_runtime.h>
#include <math.h>
#include <stdint.h>

#define T_TOK 8192
#define HIDDEN 2048
#define NH 16
#define NKV 4
#define HD 128
#define BATCH 8
#define SEQ 1024

// -------- scratch (device globals: no allocation allowed) --------
__device__ float g_q[(size_t)T_TOK * NH * HD];     // 64 MB
__device__ float g_k[(size_t)T_TOK * NKV * HD];    // 16 MB
__device__ float g_v[(size_t)T_TOK * NKV * HD];    // 16 MB
__device__ float g_o[(size_t)T_TOK * NH * HD];     // 64 MB
__device__ int   g_perm[T_TOK];
__device__ int   g_n0;

// =================================================================
// 1) stable partition of tokens by route (gen_mask>0)
// =================================================================
__global__ void partition_kernel(const int* __restrict__ gm) {
    __shared__ int sc[1024];
    int tid = threadIdx.x;
    int base = tid * 8;
    int z = 0;
#pragma unroll
    for (int i = 0; i < 8; i++) z += (gm[base + i] > 0) ? 0 : 1;
    sc[tid] = z;
    __syncthreads();
    // inclusive scan (Hillis-Steele)
    for (int off = 1; off < 1024; off <<= 1) {
        int v = (tid >= off) ? sc[tid - off] : 0;
        __syncthreads();
        sc[tid] += v;
        __syncthreads();
    }
    int total0 = sc[1023];
    int zpos = sc[tid] - z;     // zeros before my chunk
    int opos = base - zpos;     // ones before my chunk
#pragma unroll
    for (int i = 0; i < 8; i++) {
        int t = base + i;
        if (gm[t] > 0) g_perm[total0 + opos++] = t;
        else           g_perm[zpos++] = t;
    }
    if (tid == 0) g_n0 = total0;
}

// =================================================================
// 2) routed SGEMM:  C[perm[r], c] = X[perm[r], :] @ Wsel[c, :]^T + bsel[c]
//    BM=BN=128, BK=8, 256 threads, 8x8 microtile. K fixed = 2048.
// =================================================================
__global__ __launch_bounds__(256)
void gemm_routed(const float* __restrict__ X,
                 const float* __restrict__ W0, const float* __restrict__ W1,
                 const float* __restrict__ b0, const float* __restrict__ b1,
                 float* __restrict__ C, int N) {
    __shared__ float Xs[8 * 128];
    __shared__ float Ws0[8 * 128];
    __shared__ float Ws1[8 * 128];
    __shared__ int Prm[128];

    const int tid = threadIdx.x;
    const int tx = tid & 15, ty = tid >> 4;
    const int r0 = blockIdx.y * 128, c0 = blockIdx.x * 128;
    const int n0 = g_n0;

    if (tid < 128) Prm[tid] = g_perm[r0 + tid];
    __syncthreads();

    const bool allA = (r0 + 128 <= n0);
    const bool allB = (r0 >= n0);

    float acc[8][8];
#pragma unroll
    for (int i = 0; i < 8; i++)
#pragma unroll
        for (int j = 0; j < 8; j++) acc[i][j] = 0.0f;

    const int m = tid >> 1;
    const int kq = (tid & 1) * 4;
    const size_t xrow = (size_t)Prm[m] * HIDDEN;
    const size_t wrow = (size_t)(c0 + m) * HIDDEN;

    if (allA || allB) {
        const float* __restrict__ Wu = allB ? W1 : W0;
        for (int k0 = 0; k0 < HIDDEN; k0 += 8) {
            float4 xv = *(const float4*)(X + xrow + k0 + kq);
            float4 wv = *(const float4*)(Wu + wrow + k0 + kq);
            Xs[(kq + 0) * 128 + m] = xv.x; Xs[(kq + 1) * 128 + m] = xv.y;
            Xs[(kq + 2) * 128 + m] = xv.z; Xs[(kq + 3) * 128 + m] = xv.w;
            Ws0[(kq + 0) * 128 + m] = wv.x; Ws0[(kq + 1) * 128 + m] = wv.y;
            Ws0[(kq + 2) * 128 + m] = wv.z; Ws0[(kq + 3) * 128 + m] = wv.w;
            __syncthreads();
#pragma unroll
            for (int kk = 0; kk < 8; kk++) {
                float4 xa = *(const float4*)&Xs[kk * 128 + ty * 8];
                float4 xb = *(const float4*)&Xs[kk * 128 + ty * 8 + 4];
                float4 wa = *(const float4*)&Ws0[kk * 128 + tx * 8];
                float4 wb = *(const float4*)&Ws0[kk * 128 + tx * 8 + 4];
                float xf[8] = {xa.x, xa.y, xa.z, xa.w, xb.x, xb.y, xb.z, xb.w};
                float wf[8] = {wa.x, wa.y, wa.z, wa.w, wb.x, wb.y, wb.z, wb.w};
#pragma unroll
                for (int i = 0; i < 8; i++)
#pragma unroll
                    for (int j = 0; j < 8; j++) acc[i][j] += xf[i] * wf[j];
            }
            __syncthreads();
        }
    } else {
        // boundary tile: mixed routes, per-row weight select (rare: <=1 row-block)
        bool rb[8];
#pragma unroll
        for (int i = 0; i < 8; i++) rb[i] = (r0 + ty * 8 + i) >= n0;
        for (int k0 = 0; k0 < HIDDEN; k0 += 8) {
            float4 xv = *(const float4*)(X + xrow + k0 + kq);
            float4 w0v = *(const float4*)(W0 + wrow + k0 + kq);
            float4 w1v = *(const float4*)(W1 + wrow + k0 + kq);
            Xs[(kq + 0) * 128 + m] = xv.x; Xs[(kq + 1) * 128 + m] = xv.y;
            Xs[(kq + 2) * 128 + m] = xv.z; Xs[(kq + 3) * 128 + m] = xv.w;
            Ws0[(kq + 0) * 128 + m] = w0v.x; Ws0[(kq + 1) * 128 + m] = w0v.y;
            Ws0[(kq + 2) * 128 + m] = w0v.z; Ws0[(kq + 3) * 128 + m] = w0v.w;
            Ws1[(kq + 0) * 128 + m] = w1v.x; Ws1[(kq + 1) * 128 + m] = w1v.y;
            Ws1[(kq + 2) * 128 + m] = w1v.z; Ws1[(kq + 3) * 128 + m] = w1v.w;
            __syncthreads();
#pragma unroll
            for (int kk = 0; kk < 8; kk++) {
                float xf[8], w0f[8], w1f[8];
#pragma unroll
                for (int i = 0; i < 8; i++) xf[i] = Xs[kk * 128 + ty * 8 + i];
#pragma unroll
                for (int j = 0; j < 8; j++) {
                    w0f[j] = Ws0[kk * 128 + tx * 8 + j];
                    w1f[j] = Ws1[kk * 128 + tx * 8 + j];
                }
#pragma unroll
                for (int i = 0; i < 8; i++)
#pragma unroll
                    for (int j = 0; j < 8; j++)
                        acc[i][j] += xf[i] * (rb[i] ? w1f[j] : w0f[j]);
            }
            __syncthreads();
        }
    }

#pragma unroll
    for (int i = 0; i < 8; i++) {
        int gr = r0 + ty * 8 + i;
        int tok = Prm[ty * 8 + i];
        bool rt = gr >= n0;
        const float* bb = rt ? b1 : b0;
        int cbase = c0 + tx * 8;
        float4 o0, o1;
        o0.x = acc[i][0]; o0.y = acc[i][1]; o0.z = acc[i][2]; o0.w = acc[i][3];
        o1.x = acc[i][4]; o1.y = acc[i][5]; o1.z = acc[i][6]; o1.w = acc[i][7];
        if (bb) {
            o0.x += bb[cbase + 0]; o0.y += bb[cbase + 1];
            o0.z += bb[cbase + 2]; o0.w += bb[cbase + 3];
            o1.x += bb[cbase + 4]; o1.y += bb[cbase + 5];
            o1.z += bb[cbase + 6]; o1.w += bb[cbase + 7];
        }
        float* cp = C + (size_t)tok * N + cbase;
        *(float4*)(cp) = o0;
        *(float4*)(cp + 4) = o1;
    }
}

// =================================================================
// 3) fused per-head RMS norm + RoPE (one warp per (token, head))
// =================================================================
__global__ void rmsrope_kernel(const int* __restrict__ gm,
                               const float* __restrict__ cosb,
                               const float* __restrict__ sinb,
                               const float* __restrict__ qw,
                               const float* __restrict__ qwg,
                               const float* __restrict__ kw,
                               const float* __restrict__ kwg) {
    const int warp = (blockIdx.x * blockDim.x + threadIdx.x) >> 5;
    const int lane = threadIdx.x & 31;
    const int QP = T_TOK * NH;
    const int TOTAL = QP + T_TOK * NKV;
    if (warp >= TOTAL) return;

    float* ptr;
    const float* w;
    int t;
    if (warp < QP) {
        t = warp >> 4;
        ptr = g_q + (size_t)warp * HD;
        bool rt = gm[t] > 0;
        w = rt ? qwg : qw;
    } else {
        int p = warp - QP;
        t = p >> 2;
        ptr = g_k + (size_t)p * HD;
        bool rt = gm[t] > 0;
        w = rt ? kwg : kw;
    }

    float v[4];
#pragma unroll
    for (int r = 0; r < 4; r++) v[r] = ptr[lane + 32 * r];
    float ss = v[0] * v[0] + v[1] * v[1] + v[2] * v[2] + v[3] * v[3];
#pragma unroll
    for (int off = 16; off > 0; off >>= 1)
        ss += __shfl_xor_sync(0xffffffffu, ss, off);
    float rs = rsqrtf(ss * (1.0f / 128.0f) + 1e-6f);

#pragma unroll
    for (int r = 0; r < 4; r++) {
        int d = lane + 32 * r;
        v[r] = v[r] * rs * w[d];
    }
    // rope: d<64 -> rot=-x[d+64]; d>=64 -> rot=x[d-64]
    float rot[4] = {-v[2], -v[3], v[0], v[1]};
#pragma unroll
    for (int r = 0; r < 4; r++) {
        int d = lane + 32 * r;
        float c = cosb[(size_t)t * HD + d];
        float s = sinb[(size_t)t * HD + d];
        ptr[d] = v[r] * c + rot[r] * s;
    }
}

// =================================================================
// 4) flash attention, fp32, causal, GQA (kv head = h/4)
//    grid (L/64, H, B), 256 threads, BM=BN=64, D=128
// =================================================================
#define ATT_SMEM_FLOATS (128 * 65 + 128 * 65 + 64 * 132 + 64 * 65)

__global__ __launch_bounds__(256)
void attn_kernel(const float* __restrict__ q, const float* __restrict__ k,
                 const float* __restrict__ v, float* __restrict__ o) {
    extern __shared__ float sm[];
    float* Qs = sm;                 // [d][m] stride 65
    float* Ks = Qs + 128 * 65;      // [d][n] stride 65
    float* Vs = Ks + 128 * 65;      // [n][d] stride 132
    float* Ps = Vs + 64 * 132;      // [j][i] stride 65

    const int tid = threadIdx.x;
    const int tx = tid & 15, ty = tid >> 4;
    const int qb = blockIdx.x, h = blockIdx.y, b = blockIdx.z;
    const int kvh = h >> 2;
    const float scale = 0.08838834764831845f; // 1/sqrt(128)

    // load Q transposed, pre-scaled
    for (int idx = tid; idx < 64 * 128; idx += 256) {
        int mm = idx >> 7, d = idx & 127;
        Qs[d * 65 + mm] =
            q[(((size_t)(b * SEQ + qb * 64 + mm)) * NH + h) * HD + d] * scale;
    }

    float mi[4], li[4], acc[4][8];
#pragma unroll
    for (int i = 0; i < 4; i++) {
        mi[i] = -1e30f; li[i] = 0.0f;
#pragma unroll
        for (int j = 0; j < 8; j++) acc[i][j] = 0.0f;
    }

    for (int kb = 0; kb <= qb; kb++) {
        __syncthreads();
        for (int idx = tid; idx < 64 * 128; idx += 256) {
            int n = idx >> 7, d = idx & 127;
            size_t g = (((size_t)(b * SEQ + kb * 64 + n)) * NKV + kvh) * HD + d;
            Ks[d * 65 + n] = k[g];
            Vs[n * 132 + d] = v[g];
        }
        __syncthreads();

        float s[4][4];
#pragma unroll
        for (int i = 0; i < 4; i++)
#pragma unroll
            for (int j = 0; j < 4; j++) s[i][j] = 0.0f;

#pragma unroll 4
        for (int d = 0; d < 128; d++) {
            float qf[4], kf[4];
#pragma unroll
            for (int i = 0; i < 4; i++) qf[i] = Qs[d * 65 + ty * 4 + i];
#pragma unroll
            for (int j = 0; j < 4; j++) kf[j] = Ks[d * 65 + tx * 4 + j];
#pragma unroll
            for (int i = 0; i < 4; i++)
#pragma unroll
                for (int j = 0; j < 4; j++) s[i][j] += qf[i] * kf[j];
        }

        if (kb == qb) {
#pragma unroll
            for (int i = 0; i < 4; i++)
#pragma unroll
                for (int j = 0; j < 4; j++)
                    if (tx * 4 + j > ty * 4 + i) s[i][j] = -1e30f;
        }

        // online softmax per row (16-lane reduce across tx group)
#pragma unroll
        for (int i = 0; i < 4; i++) {
            float rm = fmaxf(fmaxf(s[i][0], s[i][1]), fmaxf(s[i][2], s[i][3]));
#pragma unroll
            for (int off = 8; off > 0; off >>= 1)
                rm = fmaxf(rm, __shfl_xor_sync(0xffffffffu, rm, off));
            float mn = fmaxf(mi[i], rm);
            float corr = __expf(mi[i] - mn);
            float ps = 0.0f;
#pragma unroll
            for (int j = 0; j < 4; j++) {
                float p = __expf(s[i][j] - mn);
                s[i][j] = p;
                ps += p;
            }
#pragma unroll
            for (int off = 8; off > 0; off >>= 1)
                ps += __shfl_xor_sync(0xffffffffu, ps, off);
            li[i] = li[i] * corr + ps;
            mi[i] = mn;
#pragma unroll
            for (int j = 0; j < 8; j++) acc[i][j] *= corr;
        }

        // stage P transposed [j][i]
#pragma unroll
        for (int i = 0; i < 4; i++)
#pragma unroll
            for (int j = 0; j < 4; j++)
                Ps[(tx * 4 + j) * 65 + ty * 4 + i] = s[i][j];
        __syncthreads();

        // O += P @ V
#pragma unroll 2
        for (int j = 0; j < 64; j++) {
            float pf[4];
#pragma unroll
            for (int i = 0; i < 4; i++) pf[i] = Ps[j * 65 + ty * 4 + i];
            float4 va = *(const float4*)&Vs[j * 132 + tx * 8];
            float4 vb = *(const float4*)&Vs[j * 132 + tx * 8 + 4];
            float vf[8] = {va.x, va.y, va.z, va.w, vb.x, vb.y, vb.z, vb.w};
#pragma unroll
            for (int i = 0; i < 4; i++)
#pragma unroll
                for (int jj = 0; jj < 8; jj++) acc[i][jj] += pf[i] * vf[jj];
        }
    }

#pragma unroll
    for (int i = 0; i < 4; i++) {
        float inv = 1.0f / li[i];
        float* op = o + (((size_t)(b * SEQ + qb * 64 + ty * 4 + i)) * NH + h) * HD + tx * 8;
        float4 o0, o1;
        o0.x = acc[i][0] * inv; o0.y = acc[i][1] * inv;
        o0.z = acc[i][2] * inv; o0.w = acc[i][3] * inv;
        o1.x = acc[i][4] * inv; o1.y = acc[i][5] * inv;
        o1.z = acc[i][6] * inv; o1.w = acc[i][7] * inv;
        *(float4*)(op) = o0;
        *(float4*)(op + 4) = o1;
    }
}

// =================================================================
// launch
// =================================================================
extern "C" void kernel_launch(void* const* d_in, const int* in_sizes, int n_in,
                              void* d_out, int out_size) {
    const float* x    = (const float*)d_in[0];
    const float* cosb = (const float*)d_in[1];
    const float* sinb = (const float*)d_in[2];
    // d_in[3] = attn_bias (exactly causal 0/-1e9; applied analytically)
    const int*   gm   = (const int*)d_in[4];
    const float* Wq   = (const float*)d_in[5];
    const float* bq   = (const float*)d_in[6];
    const float* Wqg  = (const float*)d_in[7];
    const float* bqg  = (const float*)d_in[8];
    const float* Wk   = (const float*)d_in[9];
    const float* bk   = (const float*)d_in[10];
    const float* Wkg  = (const float*)d_in[11];
    const float* bkg  = (const float*)d_in[12];
    const float* Wv   = (const float*)d_in[13];
    const float* bv   = (const float*)d_in[14];
    const float* Wvg  = (const float*)d_in[15];
    const float* bvg  = (const float*)d_in[16];
    const float* Wo   = (const float*)d_in[17];
    const float* Wog  = (const float*)d_in[18];
    const float* qw   = (const float*)d_in[19];
    const float* qwg  = (const float*)d_in[20];
    const float* kw   = (const float*)d_in[21];
    const float* kwg  = (const float*)d_in[22];
    float* out = (float*)d_out;

    void *pq, *pk, *pv, *po;
    cudaGetSymbolAddress(&pq, g_q);
    cudaGetSymbolAddress(&pk, g_k);
    cudaGetSymbolAddress(&pv, g_v);
    cudaGetSymbolAddress(&po, g_o);
    float* qbuf = (float*)pq;
    float* kbuf = (float*)pk;
    float* vbuf = (float*)pv;
    float* obuf = (float*)po;

    static const size_t att_smem = ATT_SMEM_FLOATS * sizeof(float);
    cudaFuncSetAttribute(attn_kernel, cudaFuncAttributeMaxDynamicSharedMemorySize,
                         (int)att_smem);

    // 1) partition tokens by route
    partition_kernel<<<1, 1024>>>(gm);

    // 2) routed QKV projections (gathered rows via perm, 1x flops)
    gemm_routed<<<dim3(NH * HD / 128, T_TOK / 128), 256>>>(
        x, Wq, Wqg, bq, bqg, qbuf, NH * HD);
    gemm_routed<<<dim3(NKV * HD / 128, T_TOK / 128), 256>>>(
        x, Wk, Wkg, bk, bkg, kbuf, NKV * HD);
    gemm_routed<<<dim3(NKV * HD / 128, T_TOK / 128), 256>>>(
        x, Wv, Wvg, bv, bvg, vbuf, NKV * HD);

    // 3) RMS norm + RoPE (in place on qbuf/kbuf)
    {
        int warps = T_TOK * (NH + NKV);
        int blocks = (warps * 32 + 255) / 256;
        rmsrope_kernel<<<blocks, 256>>>(gm, cosb, sinb, qw, qwg, kw, kwg);
    }

    // 4) causal GQA flash attention
    attn_kernel<<<dim3(SEQ / 64, NH, BATCH), 256, att_smem>>>(
        qbuf, kbuf, vbuf, obuf);

    // 5) routed output projection -> d_out
    gemm_routed<<<dim3(HIDDEN / 128, T_TOK / 128), 256>>>(
        obuf, Wo, Wog, nullptr, nullptr, out, HIDDEN);
}

// round 4
// speedup vs baseline: 2.4580x; 2.4513x over previous
#include <cuda_runtime.h>
#include <cuda_bf16.h>
#include <math.h>
#include <stdint.h>

#define T_TOK 8192
#define HIDDEN 2048
#define NH 16
#define NKV 4
#define HD 128
#define BATCH 8
#define SEQ 1024

#define BM 128
#define BN 128
#define BK 64
#define NCH (HIDDEN / BK)          // 32
#define ROWBLKS (T_TOK / BM)       // 64

// smem per stage: Ah | Al | Bh | Bl, each 128x64 bf16 = 16 KB
#define TILE_B 16384
#define STG (4 * TILE_B)           // 64 KB
#define GSMEM (3 * STG)            // 192 KB, 3-stage pipeline

// -------- scratch --------
__device__ float g_q[(size_t)T_TOK * NH * HD];
__device__ float g_k[(size_t)T_TOK * NKV * HD];
__device__ float g_v[(size_t)T_TOK * NKV * HD];
__device__ float g_o[(size_t)T_TOK * NH * HD];
__device__ int   g_perm[T_TOK];
__device__ int   g_n0;

__device__ __nv_bfloat16 g_xh[(size_t)T_TOK * HIDDEN];
__device__ __nv_bfloat16 g_xl[(size_t)T_TOK * HIDDEN];
__device__ __nv_bfloat16 g_wqh[2048*2048],  g_wql[2048*2048];
__device__ __nv_bfloat16 g_wqgh[2048*2048], g_wqgl[2048*2048];
__device__ __nv_bfloat16 g_wkh[512*2048],   g_wkl[512*2048];
__device__ __nv_bfloat16 g_wkgh[512*2048],  g_wkgl[512*2048];
__device__ __nv_bfloat16 g_wvh[512*2048],   g_wvl[512*2048];
__device__ __nv_bfloat16 g_wvgh[512*2048],  g_wvgl[512*2048];
__device__ __nv_bfloat16 g_woh[2048*2048],  g_wol[2048*2048];
__device__ __nv_bfloat16 g_wogh[2048*2048], g_wogl[2048*2048];

// -------- asm helpers (all valid on plain compute_103) --------
__device__ __forceinline__ uint32_t smem_to_u32(const void* p) {
    uint32_t a;
    asm("{ .reg .u64 t; cvta.to.shared.u64 t, %1; cvt.u32.u64 %0, t; }"
        : "=r"(a) : "l"(p));
    return a;
}
#define CPA(dst, src) asm volatile( \
    "cp.async.cg.shared.global [%0], [%1], 16;" \
    :: "r"(dst), "l"(src) : "memory")
#define CPC() asm volatile("cp.async.commit_group;" ::: "memory")
#define CPW(n) asm volatile("cp.async.wait_group %0;" :: "n"(n) : "memory")

#define LDSM4(r, a) asm volatile( \
    "ldmatrix.sync.aligned.m8n8.x4.shared.b16 {%0,%1,%2,%3}, [%4];" \
    : "=r"((r)[0]), "=r"((r)[1]), "=r"((r)[2]), "=r"((r)[3]) : "r"(a))

#define MMA_BF16(d, a, b0, b1) asm volatile( \
    "mma.sync.aligned.m16n8k16.row.col.f32.bf16.bf16.f32 " \
    "{%0,%1,%2,%3}, {%4,%5,%6,%7}, {%8,%9}, {%0,%1,%2,%3};" \
    : "+f"((d)[0]), "+f"((d)[1]), "+f"((d)[2]), "+f"((d)[3]) \
    : "r"((a)[0]), "r"((a)[1]), "r"((a)[2]), "r"((a)[3]), "r"(b0), "r"(b1))

// -------- partition --------
__global__ void partition_kernel(const int* __restrict__ gm) {
    __shared__ int sc[1024];
    int tid = threadIdx.x, base = tid * 8, z = 0;
#pragma unroll
    for (int i = 0; i < 8; i++) z += (gm[base + i] > 0) ? 0 : 1;
    sc[tid] = z;
    __syncthreads();
    for (int off = 1; off < 1024; off <<= 1) {
        int v = (tid >= off) ? sc[tid - off] : 0;
        __syncthreads();
        sc[tid] += v;
        __syncthreads();
    }
    int total0 = sc[1023], zpos = sc[tid] - z, opos = base - zpos;
#pragma unroll
    for (int i = 0; i < 8; i++) {
        int t = base + i;
        if (gm[t] > 0) g_perm[total0 + opos++] = t;
        else           g_perm[zpos++] = t;
    }
    if (tid == 0) g_n0 = total0;
}

// -------- fp32 -> bf16 hi/lo split --------
__device__ __forceinline__ void split4(float4 v, uint2& H, uint2& L) {
    __nv_bfloat16 h0 = __float2bfloat16(v.x), h1 = __float2bfloat16(v.y);
    __nv_bfloat16 h2 = __float2bfloat16(v.z), h3 = __float2bfloat16(v.w);
    __nv_bfloat16 l0 = __float2bfloat16(v.x - __bfloat162float(h0));
    __nv_bfloat16 l1 = __float2bfloat16(v.y - __bfloat162float(h1));
    __nv_bfloat16 l2 = __float2bfloat16(v.z - __bfloat162float(h2));
    __nv_bfloat16 l3 = __float2bfloat16(v.w - __bfloat162float(h3));
    H.x = ((uint32_t)__bfloat16_as_ushort(h1) << 16) | __bfloat16_as_ushort(h0);
    H.y = ((uint32_t)__bfloat16_as_ushort(h3) << 16) | __bfloat16_as_ushort(h2);
    L.x = ((uint32_t)__bfloat16_as_ushort(l1) << 16) | __bfloat16_as_ushort(l0);
    L.y = ((uint32_t)__bfloat16_as_ushort(l3) << 16) | __bfloat16_as_ushort(l2);
}
__global__ void cvt_perm(const float* __restrict__ src,
                         __nv_bfloat16* __restrict__ hi,
                         __nv_bfloat16* __restrict__ lo) {
    int i = blockIdx.x * 256 + threadIdx.x;
    int r = i >> 9, c4 = i & 511;
    float4 v = ((const float4*)(src + (size_t)g_perm[r] * HIDDEN))[c4];
    uint2 H, L;
    split4(v, H, L);
    ((uint2*)hi)[i] = H;
    ((uint2*)lo)[i] = L;
}
__global__ void cvt_plain(const float* __restrict__ src,
                          __nv_bfloat16* __restrict__ hi,
                          __nv_bfloat16* __restrict__ lo) {
    int i = blockIdx.x * 256 + threadIdx.x;
    float4 v = ((const float4*)src)[i];
    uint2 H, L;
    split4(v, H, L);
    ((uint2*)hi)[i] = H;
    ((uint2*)lo)[i] = L;
}

// =================================================================
// mma.sync bf16 routed GEMM (3-term fp32 emulation)
// grid: (N/BN, ROWBLKS+1), 256 threads
// =================================================================
__global__ __launch_bounds__(256, 1)
void gemm_mma(const __nv_bfloat16* __restrict__ Agh,
              const __nv_bfloat16* __restrict__ Agl,
              const __nv_bfloat16* __restrict__ B0h,
              const __nv_bfloat16* __restrict__ B0l,
              const __nv_bfloat16* __restrict__ B1h,
              const __nv_bfloat16* __restrict__ B1l,
              const float* __restrict__ bias0,
              const float* __restrict__ bias1,
              float* __restrict__ C, int N) {
    const int n0 = g_n0;
    int rowblk, wlo, whi;
    bool useW1;
    if (blockIdx.y < ROWBLKS) {
        rowblk = blockIdx.y;
        int lo = rowblk * BM, hi2 = lo + BM;
        if (hi2 <= n0)     { useW1 = false; wlo = lo; whi = hi2; }
        else if (lo >= n0) { useW1 = true;  wlo = lo; whi = hi2; }
        else               { useW1 = false; wlo = lo; whi = n0;  }
    } else {
        if ((n0 & (BM - 1)) == 0) return;   // no mixed block
        rowblk = n0 / BM; useW1 = true; wlo = n0; whi = rowblk * BM + BM;
    }
    const int row0 = rowblk * BM;
    const int col0 = blockIdx.x * BN;

    extern __shared__ char smem[];
    const uint32_t sb = smem_to_u32(smem);
    const int tid = threadIdx.x, wid = tid >> 5, lane = tid & 31;
    const int mbase = (wid & 1) * 64;      // 2 m-warps
    const int nbase = (wid >> 1) * 32;     // 4 n-warps

    const __nv_bfloat16* __restrict__ Bh = useW1 ? B1h : B0h;
    const __nv_bfloat16* __restrict__ Bl = useW1 ? B1l : B0l;

    // ---- per-thread load indices (4 iters x 4 tiles of cp.async 16B) ----
    // idx = tid + 256*it : row = idx>>3 (0..127), chunk = idx&7 (16B units)
    // smem off = row*128 + ((chunk ^ (row&7))<<4)
    float acc[4][4][4];
#pragma unroll
    for (int a = 0; a < 4; a++)
#pragma unroll
        for (int b = 0; b < 4; b++)
#pragma unroll
            for (int c = 0; c < 4; c++) acc[a][b][c] = 0.0f;

#define LOAD_STAGE(ST, CH) do {                                            \
    uint32_t _base = sb + (ST) * STG;                                      \
    int _k0 = (CH) * BK;                                                   \
    _Pragma("unroll")                                                      \
    for (int _it = 0; _it < 4; _it++) {                                    \
        int _idx = tid + _it * 256;                                        \
        int _row = _idx >> 3, _c = _idx & 7;                               \
        uint32_t _d = _base + _row * 128 + (((_c ^ (_row & 7))) << 4);     \
        size_t _ga = (size_t)(row0 + _row) * HIDDEN + _k0 + _c * 8;        \
        size_t _gb = (size_t)(col0 + _row) * HIDDEN + _k0 + _c * 8;        \
        CPA(_d,                Agh + _ga);                                 \
        CPA(_d + TILE_B,       Agl + _ga);                                 \
        CPA(_d + 2 * TILE_B,   Bh + _gb);                                  \
        CPA(_d + 3 * TILE_B,   Bl + _gb);                                  \
    }                                                                      \
    CPC();                                                                 \
} while (0)

    LOAD_STAGE(0, 0);
    LOAD_STAGE(1, 1);

    const int q = lane >> 3, rr = lane & 7;
    // A frag source rows/chunks
    const int arow_off = (q & 1) * 8 + rr;       // + mbase + mt*16
    const int achk_off = (q >> 1);               // + ks*2
    // B frag source rows/chunks
    const int brow_off = (q >> 1) * 8 + rr;      // + nbase + nb*16
    const int bchk_off = (q & 1);                // + ks*2

    for (int ch = 0; ch < NCH; ch++) {
        CPW(1);
        __syncthreads();
        if (ch + 2 < NCH) LOAD_STAGE((ch + 2) % 3, ch + 2);

        const uint32_t so = sb + (ch % 3) * STG;
#pragma unroll
        for (int ks = 0; ks < 4; ks++) {
            uint32_t ah[4][4], al[4][4], bh[2][4], bl[2][4];
#pragma unroll
            for (int mt = 0; mt < 4; mt++) {
                int row = mbase + mt * 16 + arow_off;
                int chk = ks * 2 + achk_off;
                uint32_t ad = so + row * 128 + (((chk << 4)) ^ ((row & 7) << 4));
                LDSM4(ah[mt], ad);
                LDSM4(al[mt], ad + TILE_B);
            }
#pragma unroll
            for (int nb = 0; nb < 2; nb++) {
                int row = nbase + nb * 16 + brow_off;
                int chk = ks * 2 + bchk_off;
                uint32_t bd = so + 2 * TILE_B + row * 128 +
                              (((chk << 4)) ^ ((row & 7) << 4));
                LDSM4(bh[nb], bd);
                LDSM4(bl[nb], bd + TILE_B);
            }
#pragma unroll
            for (int mt = 0; mt < 4; mt++)
#pragma unroll
                for (int nt = 0; nt < 4; nt++) {
                    int nb = nt >> 1, i0 = (nt & 1) * 2;
                    MMA_BF16(acc[mt][nt], ah[mt], bh[nb][i0], bh[nb][i0 + 1]);
                    MMA_BF16(acc[mt][nt], ah[mt], bl[nb][i0], bl[nb][i0 + 1]);
                    MMA_BF16(acc[mt][nt], al[mt], bh[nb][i0], bh[nb][i0 + 1]);
                }
        }
        __syncthreads();
    }

    // ---- epilogue: c frag lane mapping: rows l>>2, l>>2+8; cols 2*(l&3) ----
    const float* bias = useW1 ? bias1 : bias0;
#pragma unroll
    for (int mt = 0; mt < 4; mt++) {
        int r0 = row0 + mbase + mt * 16 + (lane >> 2);
        int r1 = r0 + 8;
        bool w0 = (r0 >= wlo) && (r0 < whi);
        bool w1 = (r1 >= wlo) && (r1 < whi);
        int tok0 = w0 ? g_perm[r0] : 0;
        int tok1 = w1 ? g_perm[r1] : 0;
#pragma unroll
        for (int nt = 0; nt < 4; nt++) {
            int colg = col0 + nbase + nt * 8 + (lane & 3) * 2;
            float b0f = 0.0f, b1f = 0.0f;
            if (bias) { b0f = bias[colg]; b1f = bias[colg + 1]; }
            if (w0) {
                float2 o = {acc[mt][nt][0] + b0f, acc[mt][nt][1] + b1f};
                *(float2*)(C + (size_t)tok0 * N + colg) = o;
            }
            if (w1) {
                float2 o = {acc[mt][nt][2] + b0f, acc[mt][nt][3] + b1f};
                *(float2*)(C + (size_t)tok1 * N + colg) = o;
            }
        }
    }
#undef LOAD_STAGE
}

// -------- RMS norm + RoPE --------
__global__ void rmsrope_kernel(const int* __restrict__ gm,
                               const float* __restrict__ cosb,
                               const float* __restrict__ sinb,
                               const float* __restrict__ qw,
                               const float* __restrict__ qwg,
                               const float* __restrict__ kw,
                               const float* __restrict__ kwg) {
    const int warp = (blockIdx.x * blockDim.x + threadIdx.x) >> 5;
    const int lane = threadIdx.x & 31;
    const int QP = T_TOK * NH;
    if (warp >= QP + T_TOK * NKV) return;
    float* ptr;
    const float* w;
    int t;
    if (warp < QP) {
        t = warp >> 4;
        ptr = g_q + (size_t)warp * HD;
        w = (gm[t] > 0) ? qwg : qw;
    } else {
        int p = warp - QP;
        t = p >> 2;
        ptr = g_k + (size_t)p * HD;
        w = (gm[t] > 0) ? kwg : kw;
    }
    float v[4];
#pragma unroll
    for (int r = 0; r < 4; r++) v[r] = ptr[lane + 32 * r];
    float ss = v[0]*v[0] + v[1]*v[1] + v[2]*v[2] + v[3]*v[3];
#pragma unroll
    for (int off = 16; off > 0; off >>= 1)
        ss += __shfl_xor_sync(0xffffffffu, ss, off);
    float rs = rsqrtf(ss * (1.0f / 128.0f) + 1e-6f);
#pragma unroll
    for (int r = 0; r < 4; r++) v[r] = v[r] * rs * w[lane + 32 * r];
    float rot[4] = {-v[2], -v[3], v[0], v[1]};
#pragma unroll
    for (int r = 0; r < 4; r++) {
        int d = lane + 32 * r;
        float c = cosb[(size_t)t * HD + d];
        float s = sinb[(size_t)t * HD + d];
        ptr[d] = v[r] * c + rot[r] * s;
    }
}

// -------- flash attention (fp32) --------
#define ATT_SMEM_FLOATS (128 * 65 + 128 * 65 + 64 * 132 + 64 * 65)

__global__ __launch_bounds__(256)
void attn_kernel(const float* __restrict__ q, const float* __restrict__ k,
                 const float* __restrict__ v, float* __restrict__ o) {
    extern __shared__ float sm[];
    float* Qs = sm;
    float* Ks = Qs + 128 * 65;
    float* Vs = Ks + 128 * 65;
    float* Ps = Vs + 64 * 132;
    const int tid = threadIdx.x;
    const int tx = tid & 15, ty = tid >> 4;
    const int qb = blockIdx.x, h = blockIdx.y, b = blockIdx.z;
    const int kvh = h >> 2;
    const float scale = 0.08838834764831845f;

    for (int idx = tid; idx < 64 * 128; idx += 256) {
        int mm = idx >> 7, d = idx & 127;
        Qs[d * 65 + mm] =
            q[(((size_t)(b * SEQ + qb * 64 + mm)) * NH + h) * HD + d] * scale;
    }
    float mi[4], li[4], acc[4][8];
#pragma unroll
    for (int i = 0; i < 4; i++) {
        mi[i] = -1e30f; li[i] = 0.0f;
#pragma unroll
        for (int j = 0; j < 8; j++) acc[i][j] = 0.0f;
    }
    for (int kb = 0; kb <= qb; kb++) {
        __syncthreads();
        for (int idx = tid; idx < 64 * 128; idx += 256) {
            int n = idx >> 7, d = idx & 127;
            size_t g = (((size_t)(b * SEQ + kb * 64 + n)) * NKV + kvh) * HD + d;
            Ks[d * 65 + n] = k[g];
            Vs[n * 132 + d] = v[g];
        }
        __syncthreads();
        float s[4][4];
#pragma unroll
        for (int i = 0; i < 4; i++)
#pragma unroll
            for (int j = 0; j < 4; j++) s[i][j] = 0.0f;
#pragma unroll 4
        for (int d = 0; d < 128; d++) {
            float qf[4], kf[4];
#pragma unroll
            for (int i = 0; i < 4; i++) qf[i] = Qs[d * 65 + ty * 4 + i];
#pragma unroll
            for (int j = 0; j < 4; j++) kf[j] = Ks[d * 65 + tx * 4 + j];
#pragma unroll
            for (int i = 0; i < 4; i++)
#pragma unroll
                for (int j = 0; j < 4; j++) s[i][j] += qf[i] * kf[j];
        }
        if (kb == qb) {
#pragma unroll
            for (int i = 0; i < 4; i++)
#pragma unroll
                for (int j = 0; j < 4; j++)
                    if (tx * 4 + j > ty * 4 + i) s[i][j] = -1e30f;
        }
#pragma unroll
        for (int i = 0; i < 4; i++) {
            float rm = fmaxf(fmaxf(s[i][0], s[i][1]), fmaxf(s[i][2], s[i][3]));
#pragma unroll
            for (int off = 8; off > 0; off >>= 1)
                rm = fmaxf(rm, __shfl_xor_sync(0xffffffffu, rm, off));
            float mn = fmaxf(mi[i], rm);
            float corr = __expf(mi[i] - mn);
            float ps = 0.0f;
#pragma unroll
            for (int j = 0; j < 4; j++) {
                float p = __expf(s[i][j] - mn);
                s[i][j] = p;
                ps += p;
            }
#pragma unroll
            for (int off = 8; off > 0; off >>= 1)
                ps += __shfl_xor_sync(0xffffffffu, ps, off);
            li[i] = li[i] * corr + ps;
            mi[i] = mn;
#pragma unroll
            for (int j = 0; j < 8; j++) acc[i][j] *= corr;
        }
#pragma unroll
        for (int i = 0; i < 4; i++)
#pragma unroll
            for (int j = 0; j < 4; j++)
                Ps[(tx * 4 + j) * 65 + ty * 4 + i] = s[i][j];
        __syncthreads();
#pragma unroll 2
        for (int j = 0; j < 64; j++) {
            float pf[4];
#pragma unroll
            for (int i = 0; i < 4; i++) pf[i] = Ps[j * 65 + ty * 4 + i];
            float4 va = *(const float4*)&Vs[j * 132 + tx * 8];
            float4 vb = *(const float4*)&Vs[j * 132 + tx * 8 + 4];
            float vf[8] = {va.x, va.y, va.z, va.w, vb.x, vb.y, vb.z, vb.w};
#pragma unroll
            for (int i = 0; i < 4; i++)
#pragma unroll
                for (int jj = 0; jj < 8; jj++) acc[i][jj] += pf[i] * vf[jj];
        }
    }
#pragma unroll
    for (int i = 0; i < 4; i++) {
        float inv = 1.0f / li[i];
        float* op = o + (((size_t)(b * SEQ + qb * 64 + ty * 4 + i)) * NH + h) * HD + tx * 8;
        float4 o0, o1;
        o0.x = acc[i][0]*inv; o0.y = acc[i][1]*inv; o0.z = acc[i][2]*inv; o0.w = acc[i][3]*inv;
        o1.x = acc[i][4]*inv; o1.y = acc[i][5]*inv; o1.z = acc[i][6]*inv; o1.w = acc[i][7]*inv;
        *(float4*)(op) = o0;
        *(float4*)(op + 4) = o1;
    }
}

// -------- launch --------
extern "C" void kernel_launch(void* const* d_in, const int* in_sizes, int n_in,
                              void* d_out, int out_size) {
    const float* x    = (const float*)d_in[0];
    const float* cosb = (const float*)d_in[1];
    const float* sinb = (const float*)d_in[2];
    const int*   gm   = (const int*)d_in[4];
    const float* Wq   = (const float*)d_in[5];
    const float* bq   = (const float*)d_in[6];
    const float* Wqg  = (const float*)d_in[7];
    const float* bqg  = (const float*)d_in[8];
    const float* Wk   = (const float*)d_in[9];
    const float* bk   = (const float*)d_in[10];
    const float* Wkg  = (const float*)d_in[11];
    const float* bkg  = (const float*)d_in[12];
    const float* Wv   = (const float*)d_in[13];
    const float* bv   = (const float*)d_in[14];
    const float* Wvg  = (const float*)d_in[15];
    const float* bvg  = (const float*)d_in[16];
    const float* Wo   = (const float*)d_in[17];
    const float* Wog  = (const float*)d_in[18];
    const float* qw   = (const float*)d_in[19];
    const float* qwg  = (const float*)d_in[20];
    const float* kw   = (const float*)d_in[21];
    const float* kwg  = (const float*)d_in[22];
    float* out = (float*)d_out;

    void *pq, *pk, *pv, *po, *pxh, *pxl;
    cudaGetSymbolAddress(&pq, g_q);
    cudaGetSymbolAddress(&pk, g_k);
    cudaGetSymbolAddress(&pv, g_v);
    cudaGetSymbolAddress(&po, g_o);
    cudaGetSymbolAddress(&pxh, g_xh);
    cudaGetSymbolAddress(&pxl, g_xl);
    float *qbuf = (float*)pq, *kbuf = (float*)pk, *vbuf = (float*)pv, *obuf = (float*)po;
    __nv_bfloat16 *xh = (__nv_bfloat16*)pxh, *xl = (__nv_bfloat16*)pxl;

    void *wqh, *wql, *wqgh, *wqgl, *wkh, *wkl, *wkgh, *wkgl;
    void *wvh, *wvl, *wvgh, *wvgl, *woh, *wol, *wogh, *wogl;
    cudaGetSymbolAddress(&wqh, g_wqh);   cudaGetSymbolAddress(&wql, g_wql);
    cudaGetSymbolAddress(&wqgh, g_wqgh); cudaGetSymbolAddress(&wqgl, g_wqgl);
    cudaGetSymbolAddress(&wkh, g_wkh);   cudaGetSymbolAddress(&wkl, g_wkl);
    cudaGetSymbolAddress(&wkgh, g_wkgh); cudaGetSymbolAddress(&wkgl, g_wkgl);
    cudaGetSymbolAddress(&wvh, g_wvh);   cudaGetSymbolAddress(&wvl, g_wvl);
    cudaGetSymbolAddress(&wvgh, g_wvgh); cudaGetSymbolAddress(&wvgl, g_wvgl);
    cudaGetSymbolAddress(&woh, g_woh);   cudaGetSymbolAddress(&wol, g_wol);
    cudaGetSymbolAddress(&wogh, g_wogh); cudaGetSymbolAddress(&wogl, g_wogl);

    static const size_t att_smem = ATT_SMEM_FLOATS * sizeof(float);
    cudaFuncSetAttribute(attn_kernel, cudaFuncAttributeMaxDynamicSharedMemorySize,
                         (int)att_smem);
    cudaFuncSetAttribute(gemm_mma, cudaFuncAttributeMaxDynamicSharedMemorySize,
                         GSMEM);

    partition_kernel<<<1, 1024>>>(gm);

    cvt_perm<<<T_TOK * 512 / 256, 256>>>(x, xh, xl);
    const int NB_BIG = 2048 * 2048 / 4 / 256, NB_SM = 512 * 2048 / 4 / 256;
    cvt_plain<<<NB_BIG, 256>>>(Wq,  (__nv_bfloat16*)wqh,  (__nv_bfloat16*)wql);
    cvt_plain<<<NB_BIG, 256>>>(Wqg, (__nv_bfloat16*)wqgh, (__nv_bfloat16*)wqgl);
    cvt_plain<<<NB_SM,  256>>>(Wk,  (__nv_bfloat16*)wkh,  (__nv_bfloat16*)wkl);
    cvt_plain<<<NB_SM,  256>>>(Wkg, (__nv_bfloat16*)wkgh, (__nv_bfloat16*)wkgl);
    cvt_plain<<<NB_SM,  256>>>(Wv,  (__nv_bfloat16*)wvh,  (__nv_bfloat16*)wvl);
    cvt_plain<<<NB_SM,  256>>>(Wvg, (__nv_bfloat16*)wvgh, (__nv_bfloat16*)wvgl);
    cvt_plain<<<NB_BIG, 256>>>(Wo,  (__nv_bfloat16*)woh,  (__nv_bfloat16*)wol);
    cvt_plain<<<NB_BIG, 256>>>(Wog, (__nv_bfloat16*)wogh, (__nv_bfloat16*)wogl);

    gemm_mma<<<dim3(NH * HD / BN, ROWBLKS + 1), 256, GSMEM>>>(
        xh, xl, (__nv_bfloat16*)wqh, (__nv_bfloat16*)wql,
        (__nv_bfloat16*)wqgh, (__nv_bfloat16*)wqgl, bq, bqg, qbuf, NH * HD);
    gemm_mma<<<dim3(NKV * HD / BN, ROWBLKS + 1), 256, GSMEM>>>(
        xh, xl, (__nv_bfloat16*)wkh, (__nv_bfloat16*)wkl,
        (__nv_bfloat16*)wkgh, (__nv_bfloat16*)wkgl, bk, bkg, kbuf, NKV * HD);
    gemm_mma<<<dim3(NKV * HD / BN, ROWBLKS + 1), 256, GSMEM>>>(
        xh, xl, (__nv_bfloat16*)wvh, (__nv_bfloat16*)wvl,
        (__nv_bfloat16*)wvgh, (__nv_bfloat16*)wvgl, bv, bvg, vbuf, NKV * HD);

    {
        int warps = T_TOK * (NH + NKV);
        rmsrope_kernel<<<(warps * 32 + 255) / 256, 256>>>(gm, cosb, sinb, qw, qwg, kw, kwg);
    }

    attn_kernel<<<dim3(SEQ / 64, NH, BATCH), 256, att_smem>>>(qbuf, kbuf, vbuf, obuf);

    cvt_perm<<<T_TOK * 512 / 256, 256>>>(obuf, xh, xl);
    gemm_mma<<<dim3(HIDDEN / BN, ROWBLKS + 1), 256, GSMEM>>>(
        xh, xl, (__nv_bfloat16*)woh, (__nv_bfloat16*)wol,
        (__nv_bfloat16*)wogh, (__nv_bfloat16*)wogl, nullptr, nullptr, out, HIDDEN);
}

// round 5
// speedup vs baseline: 4.4591x; 1.8141x over previous
#include <cuda_runtime.h>
#include <cuda_bf16.h>
#include <math.h>
#include <stdint.h>

#define T_TOK 8192
#define HIDDEN 2048
#define NH 16
#define NKV 4
#define HD 128
#define BATCH 8
#define SEQ 1024

#define BM 128
#define BN 128
#define BK 64
#define NCH (HIDDEN / BK)
#define ROWBLKS (T_TOK / BM)

#define TILE_B 16384
#define STG (4 * TILE_B)
#define GSMEM (3 * STG)

// -------- scratch --------
__device__ float g_q[(size_t)T_TOK * NH * HD];
__device__ float g_k[(size_t)T_TOK * NKV * HD];
__device__ float g_v[(size_t)T_TOK * NKV * HD];
__device__ float g_o[(size_t)T_TOK * NH * HD];
__device__ int   g_perm[T_TOK];
__device__ int   g_n0;

__device__ __nv_bfloat16 g_xh[(size_t)T_TOK * HIDDEN];
__device__ __nv_bfloat16 g_xl[(size_t)T_TOK * HIDDEN];
__device__ __nv_bfloat16 g_kh[(size_t)T_TOK * NKV * HD];
__device__ __nv_bfloat16 g_kl[(size_t)T_TOK * NKV * HD];
__device__ __nv_bfloat16 g_vh[(size_t)T_TOK * NKV * HD];
__device__ __nv_bfloat16 g_vl[(size_t)T_TOK * NKV * HD];
__device__ __nv_bfloat16 g_wqh[2048*2048],  g_wql[2048*2048];
__device__ __nv_bfloat16 g_wqgh[2048*2048], g_wqgl[2048*2048];
__device__ __nv_bfloat16 g_wkh[512*2048],   g_wkl[512*2048];
__device__ __nv_bfloat16 g_wkgh[512*2048],  g_wkgl[512*2048];
__device__ __nv_bfloat16 g_wvh[512*2048],   g_wvl[512*2048];
__device__ __nv_bfloat16 g_wvgh[512*2048],  g_wvgl[512*2048];
__device__ __nv_bfloat16 g_woh[2048*2048],  g_wol[2048*2048];
__device__ __nv_bfloat16 g_wogh[2048*2048], g_wogl[2048*2048];

// -------- asm helpers --------
__device__ __forceinline__ uint32_t smem_to_u32(const void* p) {
    uint32_t a;
    asm("{ .reg .u64 t; cvta.to.shared.u64 t, %1; cvt.u32.u64 %0, t; }"
        : "=r"(a) : "l"(p));
    return a;
}
#define CPA(dst, src) asm volatile( \
    "cp.async.cg.shared.global [%0], [%1], 16;" \
    :: "r"(dst), "l"(src) : "memory")
#define CPC() asm volatile("cp.async.commit_group;" ::: "memory")
#define CPW(n) asm volatile("cp.async.wait_group %0;" :: "n"(n) : "memory")

#define LDSM4(r, a) asm volatile( \
    "ldmatrix.sync.aligned.m8n8.x4.shared.b16 {%0,%1,%2,%3}, [%4];" \
    : "=r"((r)[0]), "=r"((r)[1]), "=r"((r)[2]), "=r"((r)[3]) : "r"(a))
#define LDSM4T(r, a) asm volatile( \
    "ldmatrix.sync.aligned.m8n8.x4.trans.shared.b16 {%0,%1,%2,%3}, [%4];" \
    : "=r"((r)[0]), "=r"((r)[1]), "=r"((r)[2]), "=r"((r)[3]) : "r"(a))

#define MMA_BF16(d, a, b0, b1) asm volatile( \
    "mma.sync.aligned.m16n8k16.row.col.f32.bf16.bf16.f32 " \
    "{%0,%1,%2,%3}, {%4,%5,%6,%7}, {%8,%9}, {%0,%1,%2,%3};" \
    : "+f"((d)[0]), "+f"((d)[1]), "+f"((d)[2]), "+f"((d)[3]) \
    : "r"((a)[0]), "r"((a)[1]), "r"((a)[2]), "r"((a)[3]), "r"(b0), "r"(b1))

// -------- partition --------
__global__ void partition_kernel(const int* __restrict__ gm) {
    __shared__ int sc[1024];
    int tid = threadIdx.x, base = tid * 8, z = 0;
#pragma unroll
    for (int i = 0; i < 8; i++) z += (gm[base + i] > 0) ? 0 : 1;
    sc[tid] = z;
    __syncthreads();
    for (int off = 1; off < 1024; off <<= 1) {
        int v = (tid >= off) ? sc[tid - off] : 0;
        __syncthreads();
        sc[tid] += v;
        __syncthreads();
    }
    int total0 = sc[1023], zpos = sc[tid] - z, opos = base - zpos;
#pragma unroll
    for (int i = 0; i < 8; i++) {
        int t = base + i;
        if (gm[t] > 0) g_perm[total0 + opos++] = t;
        else           g_perm[zpos++] = t;
    }
    if (tid == 0) g_n0 = total0;
}

// -------- fp32 -> bf16 hi/lo split --------
__device__ __forceinline__ void split4(float4 v, uint2& H, uint2& L) {
    __nv_bfloat16 h0 = __float2bfloat16(v.x), h1 = __float2bfloat16(v.y);
    __nv_bfloat16 h2 = __float2bfloat16(v.z), h3 = __float2bfloat16(v.w);
    __nv_bfloat16 l0 = __float2bfloat16(v.x - __bfloat162float(h0));
    __nv_bfloat16 l1 = __float2bfloat16(v.y - __bfloat162float(h1));
    __nv_bfloat16 l2 = __float2bfloat16(v.z - __bfloat162float(h2));
    __nv_bfloat16 l3 = __float2bfloat16(v.w - __bfloat162float(h3));
    H.x = ((uint32_t)__bfloat16_as_ushort(h1) << 16) | __bfloat16_as_ushort(h0);
    H.y = ((uint32_t)__bfloat16_as_ushort(h3) << 16) | __bfloat16_as_ushort(h2);
    L.x = ((uint32_t)__bfloat16_as_ushort(l1) << 16) | __bfloat16_as_ushort(l0);
    L.y = ((uint32_t)__bfloat16_as_ushort(l3) << 16) | __bfloat16_as_ushort(l2);
}
__device__ __forceinline__ uint32_t packsplit2(float x, float y, uint32_t& lo) {
    __nv_bfloat16 hx = __float2bfloat16(x), hy = __float2bfloat16(y);
    __nv_bfloat16 lx = __float2bfloat16(x - __bfloat162float(hx));
    __nv_bfloat16 ly = __float2bfloat16(y - __bfloat162float(hy));
    lo = ((uint32_t)__bfloat16_as_ushort(ly) << 16) | __bfloat16_as_ushort(lx);
    return ((uint32_t)__bfloat16_as_ushort(hy) << 16) | __bfloat16_as_ushort(hx);
}
__global__ void cvt_perm(const float* __restrict__ src,
                         __nv_bfloat16* __restrict__ hi,
                         __nv_bfloat16* __restrict__ lo) {
    int i = blockIdx.x * 256 + threadIdx.x;
    int r = i >> 9, c4 = i & 511;
    float4 v = ((const float4*)(src + (size_t)g_perm[r] * HIDDEN))[c4];
    uint2 H, L;
    split4(v, H, L);
    ((uint2*)hi)[i] = H;
    ((uint2*)lo)[i] = L;
}
__global__ void cvt_plain(const float* __restrict__ src,
                          __nv_bfloat16* __restrict__ hi,
                          __nv_bfloat16* __restrict__ lo) {
    int i = blockIdx.x * 256 + threadIdx.x;
    float4 v = ((const float4*)src)[i];
    uint2 H, L;
    split4(v, H, L);
    ((uint2*)hi)[i] = H;
    ((uint2*)lo)[i] = L;
}

// =================================================================
// mma.sync bf16 routed GEMM (3-term fp32 emulation)
// =================================================================
__global__ __launch_bounds__(256, 1)
void gemm_mma(const __nv_bfloat16* __restrict__ Agh,
              const __nv_bfloat16* __restrict__ Agl,
              const __nv_bfloat16* __restrict__ B0h,
              const __nv_bfloat16* __restrict__ B0l,
              const __nv_bfloat16* __restrict__ B1h,
              const __nv_bfloat16* __restrict__ B1l,
              const float* __restrict__ bias0,
              const float* __restrict__ bias1,
              float* __restrict__ C, int N) {
    const int n0 = g_n0;
    int rowblk, wlo, whi;
    bool useW1;
    if (blockIdx.y < ROWBLKS) {
        rowblk = blockIdx.y;
        int lo = rowblk * BM, hi2 = lo + BM;
        if (hi2 <= n0)     { useW1 = false; wlo = lo; whi = hi2; }
        else if (lo >= n0) { useW1 = true;  wlo = lo; whi = hi2; }
        else               { useW1 = false; wlo = lo; whi = n0;  }
    } else {
        if ((n0 & (BM - 1)) == 0) return;
        rowblk = n0 / BM; useW1 = true; wlo = n0; whi = rowblk * BM + BM;
    }
    const int row0 = rowblk * BM;
    const int col0 = blockIdx.x * BN;

    extern __shared__ char smem[];
    const uint32_t sb = smem_to_u32(smem);
    const int tid = threadIdx.x, wid = tid >> 5, lane = tid & 31;
    const int mbase = (wid & 1) * 64;
    const int nbase = (wid >> 1) * 32;

    const __nv_bfloat16* __restrict__ Bh = useW1 ? B1h : B0h;
    const __nv_bfloat16* __restrict__ Bl = useW1 ? B1l : B0l;

    float acc[4][4][4];
#pragma unroll
    for (int a = 0; a < 4; a++)
#pragma unroll
        for (int b = 0; b < 4; b++)
#pragma unroll
            for (int c = 0; c < 4; c++) acc[a][b][c] = 0.0f;

#define LOAD_STAGE(ST, CH) do {                                            \
    uint32_t _base = sb + (ST) * STG;                                      \
    int _k0 = (CH) * BK;                                                   \
    _Pragma("unroll")                                                      \
    for (int _it = 0; _it < 4; _it++) {                                    \
        int _idx = tid + _it * 256;                                        \
        int _row = _idx >> 3, _c = _idx & 7;                               \
        uint32_t _d = _base + _row * 128 + (((_c ^ (_row & 7))) << 4);     \
        size_t _ga = (size_t)(row0 + _row) * HIDDEN + _k0 + _c * 8;        \
        size_t _gb = (size_t)(col0 + _row) * HIDDEN + _k0 + _c * 8;        \
        CPA(_d,                Agh + _ga);                                 \
        CPA(_d + TILE_B,       Agl + _ga);                                 \
        CPA(_d + 2 * TILE_B,   Bh + _gb);                                  \
        CPA(_d + 3 * TILE_B,   Bl + _gb);                                  \
    }                                                                      \
    CPC();                                                                 \
} while (0)

    LOAD_STAGE(0, 0);
    LOAD_STAGE(1, 1);

    const int q = lane >> 3, rr = lane & 7;
    const int arow_off = (q & 1) * 8 + rr;
    const int achk_off = (q >> 1);
    const int brow_off = (q >> 1) * 8 + rr;
    const int bchk_off = (q & 1);

    for (int ch = 0; ch < NCH; ch++) {
        CPW(1);
        __syncthreads();
        if (ch + 2 < NCH) LOAD_STAGE((ch + 2) % 3, ch + 2);

        const uint32_t so = sb + (ch % 3) * STG;
#pragma unroll
        for (int ks = 0; ks < 4; ks++) {
            uint32_t ah[4][4], al[4][4], bh[2][4], bl[2][4];
#pragma unroll
            for (int mt = 0; mt < 4; mt++) {
                int row = mbase + mt * 16 + arow_off;
                int chk = ks * 2 + achk_off;
                uint32_t ad = so + row * 128 + (((chk << 4)) ^ ((row & 7) << 4));
                LDSM4(ah[mt], ad);
                LDSM4(al[mt], ad + TILE_B);
            }
#pragma unroll
            for (int nb = 0; nb < 2; nb++) {
                int row = nbase + nb * 16 + brow_off;
                int chk = ks * 2 + bchk_off;
                uint32_t bd = so + 2 * TILE_B + row * 128 +
                              (((chk << 4)) ^ ((row & 7) << 4));
                LDSM4(bh[nb], bd);
                LDSM4(bl[nb], bd + TILE_B);
            }
#pragma unroll
            for (int mt = 0; mt < 4; mt++)
#pragma unroll
                for (int nt = 0; nt < 4; nt++) {
                    int nb = nt >> 1, i0 = (nt & 1) * 2;
                    MMA_BF16(acc[mt][nt], ah[mt], bh[nb][i0], bh[nb][i0 + 1]);
                    MMA_BF16(acc[mt][nt], ah[mt], bl[nb][i0], bl[nb][i0 + 1]);
                    MMA_BF16(acc[mt][nt], al[mt], bh[nb][i0], bh[nb][i0 + 1]);
                }
        }
        // NOTE: no trailing __syncthreads needed — next iteration's
        // post-CPW barrier orders stage reuse.
    }

    const float* bias = useW1 ? bias1 : bias0;
#pragma unroll
    for (int mt = 0; mt < 4; mt++) {
        int r0 = row0 + mbase + mt * 16 + (lane >> 2);
        int r1 = r0 + 8;
        bool w0 = (r0 >= wlo) && (r0 < whi);
        bool w1 = (r1 >= wlo) && (r1 < whi);
        int tok0 = w0 ? g_perm[r0] : 0;
        int tok1 = w1 ? g_perm[r1] : 0;
#pragma unroll
        for (int nt = 0; nt < 4; nt++) {
            int colg = col0 + nbase + nt * 8 + (lane & 3) * 2;
            float b0f = 0.0f, b1f = 0.0f;
            if (bias) { b0f = bias[colg]; b1f = bias[colg + 1]; }
            if (w0) {
                float2 o = {acc[mt][nt][0] + b0f, acc[mt][nt][1] + b1f};
                *(float2*)(C + (size_t)tok0 * N + colg) = o;
            }
            if (w1) {
                float2 o = {acc[mt][nt][2] + b0f, acc[mt][nt][3] + b1f};
                *(float2*)(C + (size_t)tok1 * N + colg) = o;
            }
        }
    }
#undef LOAD_STAGE
}

// =================================================================
// RMS norm + RoPE; emits bf16 hi/lo (Q pre-scaled by 1/sqrt(D))
// =================================================================
__global__ void rmsrope_kernel(const int* __restrict__ gm,
                               const float* __restrict__ cosb,
                               const float* __restrict__ sinb,
                               const float* __restrict__ qw,
                               const float* __restrict__ qwg,
                               const float* __restrict__ kw,
                               const float* __restrict__ kwg) {
    const int warp = (blockIdx.x * blockDim.x + threadIdx.x) >> 5;
    const int lane = threadIdx.x & 31;
    const int QP = T_TOK * NH;
    if (warp >= QP + T_TOK * NKV) return;
    const float* src;
    __nv_bfloat16 *dh, *dl;
    const float* w;
    int t;
    float oscale;
    if (warp < QP) {
        t = warp >> 4;
        src = g_q + (size_t)warp * HD;
        dh = g_xh + (size_t)warp * HD;
        dl = g_xl + (size_t)warp * HD;
        w = (gm[t] > 0) ? qwg : qw;
        oscale = 0.08838834764831845f;
    } else {
        int p = warp - QP;
        t = p >> 2;
        src = g_k + (size_t)p * HD;
        dh = g_kh + (size_t)p * HD;
        dl = g_kl + (size_t)p * HD;
        w = (gm[t] > 0) ? kwg : kw;
        oscale = 1.0f;
    }
    float v[4];
#pragma unroll
    for (int r = 0; r < 4; r++) v[r] = src[lane + 32 * r];
    float ss = v[0]*v[0] + v[1]*v[1] + v[2]*v[2] + v[3]*v[3];
#pragma unroll
    for (int off = 16; off > 0; off >>= 1)
        ss += __shfl_xor_sync(0xffffffffu, ss, off);
    float rs = rsqrtf(ss * (1.0f / 128.0f) + 1e-6f);
#pragma unroll
    for (int r = 0; r < 4; r++) v[r] = v[r] * rs * w[lane + 32 * r];
    float rot[4] = {-v[2], -v[3], v[0], v[1]};
#pragma unroll
    for (int r = 0; r < 4; r++) {
        int d = lane + 32 * r;
        float c = cosb[(size_t)t * HD + d];
        float s = sinb[(size_t)t * HD + d];
        float val = (v[r] * c + rot[r] * s) * oscale;
        __nv_bfloat16 h = __float2bfloat16(val);
        __nv_bfloat16 l = __float2bfloat16(val - __bfloat162float(h));
        dh[d] = h;
        dl[d] = l;
    }
}

// =================================================================
// FA2 attention: bf16 mma with 3-term hi/lo emulation
// CTA: 128 q-rows (8 warps x 16), 64 kv per iter, 3-stage smem ring
// =================================================================
#define A_RGN 65536
#define A_SMEM (3 * A_RGN)

__device__ __forceinline__ void load_kv_stage(
    uint32_t rgn, int tid,
    const __nv_bfloat16* __restrict__ kh, const __nv_bfloat16* __restrict__ kl,
    const __nv_bfloat16* __restrict__ vh, const __nv_bfloat16* __restrict__ vl,
    size_t gbase) {
#pragma unroll
    for (int i = 0; i < 4; i++) {
        int idx = tid + (i << 8);
        int row = idx >> 4, c = idx & 15;
        uint32_t d = rgn + row * 256 + ((c ^ (row & 7)) << 4);
        size_t g = gbase + (size_t)row * 512 + c * 8;
        CPA(d,          kh + g);
        CPA(d + 16384,  kl + g);
        CPA(d + 32768,  vh + g);
        CPA(d + 49152,  vl + g);
    }
    CPC();
}

__global__ __launch_bounds__(256, 1)
void attn_mma(const __nv_bfloat16* __restrict__ qh,
              const __nv_bfloat16* __restrict__ ql,
              const __nv_bfloat16* __restrict__ kh,
              const __nv_bfloat16* __restrict__ kl,
              const __nv_bfloat16* __restrict__ vh,
              const __nv_bfloat16* __restrict__ vl,
              float* __restrict__ o) {
    extern __shared__ char smem[];
    const uint32_t sb = smem_to_u32(smem);
    const int tid = threadIdx.x, wid = tid >> 5, lane = tid & 31;
    const int qb = blockIdx.x, h = blockIdx.y, b = blockIdx.z;
    const int kvh = h >> 2;
    const int q0 = qb * 128;
    const size_t qgbase = ((size_t)(b * SEQ + q0)) * 2048 + h * 128;
    const size_t kvgbase = ((size_t)(b * SEQ)) * 512 + kvh * 128;
    const int nkb = 2 * qb + 2;

    // Q tile -> region 0 (hi at 0, lo at +32768)
#pragma unroll
    for (int i = 0; i < 8; i++) {
        int idx = tid + (i << 8);
        int row = idx >> 4, c = idx & 15;
        uint32_t d = sb + row * 256 + ((c ^ (row & 7)) << 4);
        size_t g = qgbase + (size_t)row * 2048 + c * 8;
        CPA(d, qh + g);
        CPA(d + 32768, ql + g);
    }
    CPC();
    load_kv_stage(sb + A_RGN, tid, kh, kl, vh, vl, kvgbase);
    CPW(1);            // Q done (stage 0 may still be in flight)
    __syncthreads();

    // extract Q fragments
    const int rr = lane & 7;
    const int arow = wid * 16 + ((lane >> 3) & 1) * 8 + rr;
    const int acb = lane >> 4;
    uint32_t Qh[8][4], Ql[8][4];
#pragma unroll
    for (int kk = 0; kk < 8; kk++) {
        int ck = kk * 2 + acb;
        uint32_t ad = sb + arow * 256 + ((ck ^ (arow & 7)) << 4);
        LDSM4(Qh[kk], ad);
        LDSM4(Ql[kk], ad + 32768);
    }
    __syncthreads();   // all warps done reading Q region before it becomes stage 2
    if (nkb > 1)
        load_kv_stage(sb + 2 * A_RGN, tid, kh, kl, vh, vl, kvgbase + 64 * 512);

    float m0 = -1e30f, m1 = -1e30f, l0 = 0.0f, l1 = 0.0f;
    float oa[16][4];
#pragma unroll
    for (int i = 0; i < 16; i++)
#pragma unroll
        for (int j = 0; j < 4; j++) oa[i][j] = 0.0f;

    const int brow_off = ((lane >> 4) & 1) * 8 + rr;
    const int bcb = (lane >> 3) & 1;
    const int vrow_off = lane & 15;
    const int vcb = lane >> 4;
    const int rowg0 = q0 + wid * 16 + (lane >> 2);
    const int rowg1 = rowg0 + 8;
    const int warprow0 = q0 + wid * 16;

    for (int kb = 0; kb < nkb; kb++) {
        CPW(1);
        __syncthreads();
        if (kb + 2 < nkb)
            load_kv_stage(sb + ((kb + 3) % 3) * A_RGN, tid, kh, kl, vh, vl,
                          kvgbase + (size_t)(kb + 2) * 64 * 512);

        const uint32_t so = sb + ((kb + 1) % 3) * A_RGN;

        // ---- S = Q @ K^T ----
        float s[8][4];
#pragma unroll
        for (int i = 0; i < 8; i++)
#pragma unroll
            for (int j = 0; j < 4; j++) s[i][j] = 0.0f;

#pragma unroll
        for (int kk = 0; kk < 8; kk++) {
#pragma unroll
            for (int p = 0; p < 4; p++) {
                int krow = p * 16 + brow_off;
                int ck = kk * 2 + bcb;
                uint32_t kd = so + krow * 256 + ((ck ^ (krow & 7)) << 4);
                uint32_t bh4[4], bl4[4];
                LDSM4(bh4, kd);
                LDSM4(bl4, kd + 16384);
                MMA_BF16(s[2*p],   Qh[kk], bh4[0], bh4[1]);
                MMA_BF16(s[2*p],   Qh[kk], bl4[0], bl4[1]);
                MMA_BF16(s[2*p],   Ql[kk], bh4[0], bh4[1]);
                MMA_BF16(s[2*p+1], Qh[kk], bh4[2], bh4[3]);
                MMA_BF16(s[2*p+1], Qh[kk], bl4[2], bl4[3]);
                MMA_BF16(s[2*p+1], Ql[kk], bh4[2], bh4[3]);
            }
        }

        // ---- causal mask (only on diagonal-overlap blocks) ----
        if (kb * 64 + 63 > warprow0) {
            int colb = kb * 64 + (lane & 3) * 2;
#pragma unroll
            for (int nt = 0; nt < 8; nt++) {
                int c = colb + nt * 8;
                if (c > rowg0)     s[nt][0] = -1e30f;
                if (c + 1 > rowg0) s[nt][1] = -1e30f;
                if (c > rowg1)     s[nt][2] = -1e30f;
                if (c + 1 > rowg1) s[nt][3] = -1e30f;
            }
        }

        // ---- online softmax ----
        float mx0 = -1e30f, mx1 = -1e30f;
#pragma unroll
        for (int nt = 0; nt < 8; nt++) {
            mx0 = fmaxf(mx0, fmaxf(s[nt][0], s[nt][1]));
            mx1 = fmaxf(mx1, fmaxf(s[nt][2], s[nt][3]));
        }
        mx0 = fmaxf(mx0, __shfl_xor_sync(0xffffffffu, mx0, 1));
        mx0 = fmaxf(mx0, __shfl_xor_sync(0xffffffffu, mx0, 2));
        mx1 = fmaxf(mx1, __shfl_xor_sync(0xffffffffu, mx1, 1));
        mx1 = fmaxf(mx1, __shfl_xor_sync(0xffffffffu, mx1, 2));
        float nm0 = fmaxf(m0, mx0), nm1 = fmaxf(m1, mx1);
        float corr0 = __expf(m0 - nm0), corr1 = __expf(m1 - nm1);
        float ps0 = 0.0f, ps1 = 0.0f;
#pragma unroll
        for (int nt = 0; nt < 8; nt++) {
            s[nt][0] = __expf(s[nt][0] - nm0);
            s[nt][1] = __expf(s[nt][1] - nm0);
            s[nt][2] = __expf(s[nt][2] - nm1);
            s[nt][3] = __expf(s[nt][3] - nm1);
            ps0 += s[nt][0] + s[nt][1];
            ps1 += s[nt][2] + s[nt][3];
        }
        ps0 += __shfl_xor_sync(0xffffffffu, ps0, 1);
        ps0 += __shfl_xor_sync(0xffffffffu, ps0, 2);
        ps1 += __shfl_xor_sync(0xffffffffu, ps1, 1);
        ps1 += __shfl_xor_sync(0xffffffffu, ps1, 2);
        l0 = l0 * corr0 + ps0;
        l1 = l1 * corr1 + ps1;
        m0 = nm0; m1 = nm1;
#pragma unroll
        for (int i = 0; i < 16; i++) {
            oa[i][0] *= corr0; oa[i][1] *= corr0;
            oa[i][2] *= corr1; oa[i][3] *= corr1;
        }

        // ---- O += P @ V ----
#pragma unroll
        for (int kt = 0; kt < 4; kt++) {
            uint32_t ah4[4], al4[4];
            ah4[0] = packsplit2(s[2*kt][0],   s[2*kt][1],   al4[0]);
            ah4[1] = packsplit2(s[2*kt][2],   s[2*kt][3],   al4[1]);
            ah4[2] = packsplit2(s[2*kt+1][0], s[2*kt+1][1], al4[2]);
            ah4[3] = packsplit2(s[2*kt+1][2], s[2*kt+1][3], al4[3]);
#pragma unroll
            for (int dp = 0; dp < 8; dp++) {
                int vr = kt * 16 + vrow_off;
                int ck = dp * 2 + vcb;
                uint32_t vd = so + 32768 + vr * 256 + ((ck ^ (vr & 7)) << 4);
                uint32_t bh4[4], bl4[4];
                LDSM4T(bh4, vd);
                LDSM4T(bl4, vd + 16384);
                MMA_BF16(oa[2*dp],   ah4, bh4[0], bh4[1]);
                MMA_BF16(oa[2*dp],   ah4, bl4[0], bl4[1]);
                MMA_BF16(oa[2*dp],   al4, bh4[0], bh4[1]);
                MMA_BF16(oa[2*dp+1], ah4, bh4[2], bh4[3]);
                MMA_BF16(oa[2*dp+1], ah4, bl4[2], bl4[3]);
                MMA_BF16(oa[2*dp+1], al4, bh4[2], bh4[3]);
            }
        }
    }

    // ---- epilogue ----
    float inv0 = 1.0f / l0, inv1 = 1.0f / l1;
    size_t ob0 = ((size_t)(b * SEQ + rowg0)) * 2048 + h * 128 + (lane & 3) * 2;
    size_t ob1 = ((size_t)(b * SEQ + rowg1)) * 2048 + h * 128 + (lane & 3) * 2;
#pragma unroll
    for (int nt = 0; nt < 16; nt++) {
        float2 v0 = {oa[nt][0] * inv0, oa[nt][1] * inv0};
        float2 v1 = {oa[nt][2] * inv1, oa[nt][3] * inv1};
        *(float2*)(o + ob0 + nt * 8) = v0;
        *(float2*)(o + ob1 + nt * 8) = v1;
    }
}

// -------- launch --------
extern "C" void kernel_launch(void* const* d_in, const int* in_sizes, int n_in,
                              void* d_out, int out_size) {
    const float* x    = (const float*)d_in[0];
    const float* cosb = (const float*)d_in[1];
    const float* sinb = (const float*)d_in[2];
    const int*   gm   = (const int*)d_in[4];
    const float* Wq   = (const float*)d_in[5];
    const float* bq   = (const float*)d_in[6];
    const float* Wqg  = (const float*)d_in[7];
    const float* bqg  = (const float*)d_in[8];
    const float* Wk   = (const float*)d_in[9];
    const float* bk   = (const float*)d_in[10];
    const float* Wkg  = (const float*)d_in[11];
    const float* bkg  = (const float*)d_in[12];
    const float* Wv   = (const float*)d_in[13];
    const float* bv   = (const float*)d_in[14];
    const float* Wvg  = (const float*)d_in[15];
    const float* bvg  = (const float*)d_in[16];
    const float* Wo   = (const float*)d_in[17];
    const float* Wog  = (const float*)d_in[18];
    const float* qw   = (const float*)d_in[19];
    const float* qwg  = (const float*)d_in[20];
    const float* kw   = (const float*)d_in[21];
    const float* kwg  = (const float*)d_in[22];
    float* out = (float*)d_out;

    void *pq, *pk, *pv, *po, *pxh, *pxl, *pkh, *pkl, *pvh, *pvl;
    cudaGetSymbolAddress(&pq, g_q);
    cudaGetSymbolAddress(&pk, g_k);
    cudaGetSymbolAddress(&pv, g_v);
    cudaGetSymbolAddress(&po, g_o);
    cudaGetSymbolAddress(&pxh, g_xh);
    cudaGetSymbolAddress(&pxl, g_xl);
    cudaGetSymbolAddress(&pkh, g_kh);
    cudaGetSymbolAddress(&pkl, g_kl);
    cudaGetSymbolAddress(&pvh, g_vh);
    cudaGetSymbolAddress(&pvl, g_vl);
    float *qbuf = (float*)pq, *kbuf = (float*)pk, *vbuf = (float*)pv, *obuf = (float*)po;
    __nv_bfloat16 *xh = (__nv_bfloat16*)pxh, *xl = (__nv_bfloat16*)pxl;

    void *wqh, *wql, *wqgh, *wqgl, *wkh, *wkl, *wkgh, *wkgl;
    void *wvh, *wvl, *wvgh, *wvgl, *woh, *wol, *wogh, *wogl;
    cudaGetSymbolAddress(&wqh, g_wqh);   cudaGetSymbolAddress(&wql, g_wql);
    cudaGetSymbolAddress(&wqgh, g_wqgh); cudaGetSymbolAddress(&wqgl, g_wqgl);
    cudaGetSymbolAddress(&wkh, g_wkh);   cudaGetSymbolAddress(&wkl, g_wkl);
    cudaGetSymbolAddress(&wkgh, g_wkgh); cudaGetSymbolAddress(&wkgl, g_wkgl);
    cudaGetSymbolAddress(&wvh, g_wvh);   cudaGetSymbolAddress(&wvl, g_wvl);
    cudaGetSymbolAddress(&wvgh, g_wvgh); cudaGetSymbolAddress(&wvgl, g_wvgl);
    cudaGetSymbolAddress(&woh, g_woh);   cudaGetSymbolAddress(&wol, g_wol);
    cudaGetSymbolAddress(&wogh, g_wogh); cudaGetSymbolAddress(&wogl, g_wogl);

    cudaFuncSetAttribute(gemm_mma, cudaFuncAttributeMaxDynamicSharedMemorySize,
                         GSMEM);
    cudaFuncSetAttribute(attn_mma, cudaFuncAttributeMaxDynamicSharedMemorySize,
                         A_SMEM);

    partition_kernel<<<1, 1024>>>(gm);

    cvt_perm<<<T_TOK * 512 / 256, 256>>>(x, xh, xl);
    const int NB_BIG = 2048 * 2048 / 4 / 256, NB_SM = 512 * 2048 / 4 / 256;
    cvt_plain<<<NB_BIG, 256>>>(Wq,  (__nv_bfloat16*)wqh,  (__nv_bfloat16*)wql);
    cvt_plain<<<NB_BIG, 256>>>(Wqg, (__nv_bfloat16*)wqgh, (__nv_bfloat16*)wqgl);
    cvt_plain<<<NB_SM,  256>>>(Wk,  (__nv_bfloat16*)wkh,  (__nv_bfloat16*)wkl);
    cvt_plain<<<NB_SM,  256>>>(Wkg, (__nv_bfloat16*)wkgh, (__nv_bfloat16*)wkgl);
    cvt_plain<<<NB_SM,  256>>>(Wv,  (__nv_bfloat16*)wvh,  (__nv_bfloat16*)wvl);
    cvt_plain<<<NB_SM,  256>>>(Wvg, (__nv_bfloat16*)wvgh, (__nv_bfloat16*)wvgl);
    cvt_plain<<<NB_BIG, 256>>>(Wo,  (__nv_bfloat16*)woh,  (__nv_bfloat16*)wol);
    cvt_plain<<<NB_BIG, 256>>>(Wog, (__nv_bfloat16*)wogh, (__nv_bfloat16*)wogl);

    gemm_mma<<<dim3(NH * HD / BN, ROWBLKS + 1), 256, GSMEM>>>(
        xh, xl, (__nv_bfloat16*)wqh, (__nv_bfloat16*)wql,
        (__nv_bfloat16*)wqgh, (__nv_bfloat16*)wqgl, bq, bqg, qbuf, NH * HD);
    gemm_mma<<<dim3(NKV * HD / BN, ROWBLKS + 1), 256, GSMEM>>>(
        xh, xl, (__nv_bfloat16*)wkh, (__nv_bfloat16*)wkl,
        (__nv_bfloat16*)wkgh, (__nv_bfloat16*)wkgl, bk, bkg, kbuf, NKV * HD);
    gemm_mma<<<dim3(NKV * HD / BN, ROWBLKS + 1), 256, GSMEM>>>(
        xh, xl, (__nv_bfloat16*)wvh, (__nv_bfloat16*)wvl,
        (__nv_bfloat16*)wvgh, (__nv_bfloat16*)wvgl, bv, bvg, vbuf, NKV * HD);

    {
        int warps = T_TOK * (NH + NKV);
        rmsrope_kernel<<<(warps * 32 + 255) / 256, 256>>>(gm, cosb, sinb,
                                                          qw, qwg, kw, kwg);
    }
    // V -> bf16 hi/lo
    cvt_plain<<<T_TOK * 512 / 4 / 256, 256>>>(vbuf, (__nv_bfloat16*)pvh,
                                              (__nv_bfloat16*)pvl);

    attn_mma<<<dim3(SEQ / 128, NH, BATCH), 256, A_SMEM>>>(
        xh, xl, (__nv_bfloat16*)pkh, (__nv_bfloat16*)pkl,
        (__nv_bfloat16*)pvh, (__nv_bfloat16*)pvl, obuf);

    cvt_perm<<<T_TOK * 512 / 256, 256>>>(obuf, xh, xl);
    gemm_mma<<<dim3(HIDDEN / BN, ROWBLKS + 1), 256, GSMEM>>>(
        xh, xl, (__nv_bfloat16*)woh, (__nv_bfloat16*)wol,
        (__nv_bfloat16*)wogh, (__nv_bfloat16*)wogl, nullptr, nullptr, out, HIDDEN);
}

// round 6
// speedup vs baseline: 4.5843x; 1.0281x over previous
#include <cuda_runtime.h>
#include <cuda_bf16.h>
#include <math.h>
#include <stdint.h>

#define T_TOK 8192
#define HIDDEN 2048
#define NH 16
#define NKV 4
#define HD 128
#define BATCH 8
#define SEQ 1024

#define BM 128
#define BN 128
#define BK 64
#define NCH (HIDDEN / BK)
#define ROWBLKS (T_TOK / BM)
#define NQKV 3072              // 2048 Q + 512 K + 512 V

#define TILE_B 16384
#define STG (4 * TILE_B)
#define GSMEM (3 * STG)

// -------- scratch --------
__device__ float g_q[(size_t)T_TOK * NH * HD];
__device__ float g_k[(size_t)T_TOK * NKV * HD];
__device__ float g_o[(size_t)T_TOK * NH * HD];
__device__ int   g_perm[T_TOK];
__device__ int   g_n0;

__device__ __nv_bfloat16 g_xh[(size_t)T_TOK * HIDDEN];
__device__ __nv_bfloat16 g_xl[(size_t)T_TOK * HIDDEN];
__device__ __nv_bfloat16 g_kh[(size_t)T_TOK * NKV * HD];
__device__ __nv_bfloat16 g_kl[(size_t)T_TOK * NKV * HD];
__device__ __nv_bfloat16 g_vh[(size_t)T_TOK * NKV * HD];
__device__ __nv_bfloat16 g_vl[(size_t)T_TOK * NKV * HD];
// merged QKV weights: [Wq;Wk;Wv] 3072x2048, two routes
__device__ __nv_bfloat16 g_w0h[NQKV * 2048], g_w0l[NQKV * 2048];
__device__ __nv_bfloat16 g_w1h[NQKV * 2048], g_w1l[NQKV * 2048];
__device__ __nv_bfloat16 g_woh[2048 * 2048],  g_wol[2048 * 2048];
__device__ __nv_bfloat16 g_wogh[2048 * 2048], g_wogl[2048 * 2048];

// -------- asm helpers --------
__device__ __forceinline__ uint32_t smem_to_u32(const void* p) {
    uint32_t a;
    asm("{ .reg .u64 t; cvta.to.shared.u64 t, %1; cvt.u32.u64 %0, t; }"
        : "=r"(a) : "l"(p));
    return a;
}
#define CPA(dst, src) asm volatile( \
    "cp.async.cg.shared.global [%0], [%1], 16;" \
    :: "r"(dst), "l"(src) : "memory")
#define CPC() asm volatile("cp.async.commit_group;" ::: "memory")
#define CPW(n) asm volatile("cp.async.wait_group %0;" :: "n"(n) : "memory")

#define LDSM4(r, a) asm volatile( \
    "ldmatrix.sync.aligned.m8n8.x4.shared.b16 {%0,%1,%2,%3}, [%4];" \
    : "=r"((r)[0]), "=r"((r)[1]), "=r"((r)[2]), "=r"((r)[3]) : "r"(a))
#define LDSM4T(r, a) asm volatile( \
    "ldmatrix.sync.aligned.m8n8.x4.trans.shared.b16 {%0,%1,%2,%3}, [%4];" \
    : "=r"((r)[0]), "=r"((r)[1]), "=r"((r)[2]), "=r"((r)[3]) : "r"(a))

#define MMA_BF16(d, a, b0, b1) asm volatile( \
    "mma.sync.aligned.m16n8k16.row.col.f32.bf16.bf16.f32 " \
    "{%0,%1,%2,%3}, {%4,%5,%6,%7}, {%8,%9}, {%0,%1,%2,%3};" \
    : "+f"((d)[0]), "+f"((d)[1]), "+f"((d)[2]), "+f"((d)[3]) \
    : "r"((a)[0]), "r"((a)[1]), "r"((a)[2]), "r"((a)[3]), "r"(b0), "r"(b1))

// -------- partition --------
__global__ void partition_kernel(const int* __restrict__ gm) {
    __shared__ int sc[1024];
    int tid = threadIdx.x, base = tid * 8, z = 0;
#pragma unroll
    for (int i = 0; i < 8; i++) z += (gm[base + i] > 0) ? 0 : 1;
    sc[tid] = z;
    __syncthreads();
    for (int off = 1; off < 1024; off <<= 1) {
        int v = (tid >= off) ? sc[tid - off] : 0;
        __syncthreads();
        sc[tid] += v;
        __syncthreads();
    }
    int total0 = sc[1023], zpos = sc[tid] - z, opos = base - zpos;
#pragma unroll
    for (int i = 0; i < 8; i++) {
        int t = base + i;
        if (gm[t] > 0) g_perm[total0 + opos++] = t;
        else           g_perm[zpos++] = t;
    }
    if (tid == 0) g_n0 = total0;
}

// -------- fp32 -> bf16 hi/lo split --------
__device__ __forceinline__ void split4(float4 v, uint2& H, uint2& L) {
    __nv_bfloat16 h0 = __float2bfloat16(v.x), h1 = __float2bfloat16(v.y);
    __nv_bfloat16 h2 = __float2bfloat16(v.z), h3 = __float2bfloat16(v.w);
    __nv_bfloat16 l0 = __float2bfloat16(v.x - __bfloat162float(h0));
    __nv_bfloat16 l1 = __float2bfloat16(v.y - __bfloat162float(h1));
    __nv_bfloat16 l2 = __float2bfloat16(v.z - __bfloat162float(h2));
    __nv_bfloat16 l3 = __float2bfloat16(v.w - __bfloat162float(h3));
    H.x = ((uint32_t)__bfloat16_as_ushort(h1) << 16) | __bfloat16_as_ushort(h0);
    H.y = ((uint32_t)__bfloat16_as_ushort(h3) << 16) | __bfloat16_as_ushort(h2);
    L.x = ((uint32_t)__bfloat16_as_ushort(l1) << 16) | __bfloat16_as_ushort(l0);
    L.y = ((uint32_t)__bfloat16_as_ushort(l3) << 16) | __bfloat16_as_ushort(l2);
}
__device__ __forceinline__ uint32_t packsplit2(float x, float y, uint32_t& lo) {
    __nv_bfloat16 hx = __float2bfloat16(x), hy = __float2bfloat16(y);
    __nv_bfloat16 lx = __float2bfloat16(x - __bfloat162float(hx));
    __nv_bfloat16 ly = __float2bfloat16(y - __bfloat162float(hy));
    lo = ((uint32_t)__bfloat16_as_ushort(ly) << 16) | __bfloat16_as_ushort(lx);
    return ((uint32_t)__bfloat16_as_ushort(hy) << 16) | __bfloat16_as_ushort(hx);
}
__global__ void cvt_perm(const float* __restrict__ src,
                         __nv_bfloat16* __restrict__ hi,
                         __nv_bfloat16* __restrict__ lo) {
    int i = blockIdx.x * 256 + threadIdx.x;
    int r = i >> 9, c4 = i & 511;
    float4 v = ((const float4*)(src + (size_t)g_perm[r] * HIDDEN))[c4];
    uint2 H, L;
    split4(v, H, L);
    ((uint2*)hi)[i] = H;
    ((uint2*)lo)[i] = L;
}
__global__ void cvt_plain(const float* __restrict__ src,
                          __nv_bfloat16* __restrict__ hi,
                          __nv_bfloat16* __restrict__ lo) {
    int i = blockIdx.x * 256 + threadIdx.x;
    float4 v = ((const float4*)src)[i];
    uint2 H, L;
    split4(v, H, L);
    ((uint2*)hi)[i] = H;
    ((uint2*)lo)[i] = L;
}
// concat converter: rows [0,2048)=Wq, [2048,2560)=Wk, [2560,3072)=Wv
__global__ void cvt_qkvw(const float* __restrict__ Wq_,
                         const float* __restrict__ Wk_,
                         const float* __restrict__ Wv_,
                         __nv_bfloat16* __restrict__ hi,
                         __nv_bfloat16* __restrict__ lo) {
    int i = blockIdx.x * 256 + threadIdx.x;       // over 3072*512 float4s
    int r = i >> 9, c4 = i & 511;
    const float* src;
    if (r < 2048)       src = Wq_ + (size_t)r * 2048;
    else if (r < 2560)  src = Wk_ + (size_t)(r - 2048) * 2048;
    else                src = Wv_ + (size_t)(r - 2560) * 2048;
    float4 v = ((const float4*)src)[c4];
    uint2 H, L;
    split4(v, H, L);
    ((uint2*)hi)[i] = H;
    ((uint2*)lo)[i] = L;
}

// =================================================================
// shared GEMM mainloop (macro-free body via inline function)
// =================================================================
#define GEMM_PROLOGUE_AND_MAINLOOP(AghP, AglP, BhP, BlP)                   \
    float acc[4][4][4];                                                    \
    _Pragma("unroll")                                                      \
    for (int a = 0; a < 4; a++)                                            \
        _Pragma("unroll")                                                  \
        for (int b = 0; b < 4; b++)                                        \
            _Pragma("unroll")                                              \
            for (int c = 0; c < 4; c++) acc[a][b][c] = 0.0f;               \
    const int tid = threadIdx.x, wid = tid >> 5, lane = tid & 31;          \
    const int mbase = (wid & 1) * 64;                                      \
    const int nbase = (wid >> 1) * 32;                                     \
    extern __shared__ char smem[];                                         \
    const uint32_t sb = smem_to_u32(smem);                                 \
    const int ldrow = tid >> 3, ldc = tid & 7;                             \
    auto load_stage = [&](int st, int ch_) {                               \
        uint32_t base_ = sb + st * STG;                                    \
        int k0 = ch_ * BK;                                                 \
        _Pragma("unroll")                                                  \
        for (int it = 0; it < 4; it++) {                                   \
            int row = ldrow + it * 32;                                     \
            uint32_t d = base_ + row * 128 + ((ldc ^ (row & 7)) << 4);     \
            size_t ga = (size_t)(row0 + row) * HIDDEN + k0 + ldc * 8;      \
            size_t gb = (size_t)(col0 + row) * HIDDEN + k0 + ldc * 8;      \
            CPA(d,              AghP + ga);                                \
            CPA(d + TILE_B,     AglP + ga);                                \
            CPA(d + 2 * TILE_B, BhP + gb);                                 \
            CPA(d + 3 * TILE_B, BlP + gb);                                 \
        }                                                                  \
        CPC();                                                             \
    };                                                                     \
    load_stage(0, 0);                                                      \
    load_stage(1, 1);                                                      \
    const int q_ = lane >> 3, rr = lane & 7;                               \
    const int arow_off = (q_ & 1) * 8 + rr;                                \
    const int achk_off = (q_ >> 1);                                        \
    const int brow_off = (q_ >> 1) * 8 + rr;                               \
    const int bchk_off = (q_ & 1);                                         \
    for (int ch = 0; ch < NCH; ch++) {                                     \
        CPW(1);                                                            \
        __syncthreads();                                                   \
        if (ch + 2 < NCH) load_stage((ch + 2) % 3, ch + 2);                \
        const uint32_t so = sb + (ch % 3) * STG;                           \
        _Pragma("unroll")                                                  \
        for (int ks = 0; ks < 4; ks++) {                                   \
            uint32_t ah[4][4], al[4][4], bh[2][4], bl[2][4];               \
            _Pragma("unroll")                                              \
            for (int mt = 0; mt < 4; mt++) {                               \
                int row = mbase + mt * 16 + arow_off;                      \
                int chk = ks * 2 + achk_off;                               \
                uint32_t ad = so + row * 128 + ((chk ^ (row & 7)) << 4);   \
                LDSM4(ah[mt], ad);                                         \
                LDSM4(al[mt], ad + TILE_B);                                \
            }                                                              \
            _Pragma("unroll")                                              \
            for (int nb = 0; nb < 2; nb++) {                               \
                int row = nbase + nb * 16 + brow_off;                      \
                int chk = ks * 2 + bchk_off;                               \
                uint32_t bd = so + 2 * TILE_B + row * 128 +                \
                              ((chk ^ (row & 7)) << 4);                    \
                LDSM4(bh[nb], bd);                                         \
                LDSM4(bl[nb], bd + TILE_B);                                \
            }                                                              \
            _Pragma("unroll")                                              \
            for (int mt = 0; mt < 4; mt++)                                 \
                _Pragma("unroll")                                          \
                for (int nt = 0; nt < 4; nt++) {                           \
                    int nb = nt >> 1, i0 = (nt & 1) * 2;                   \
                    MMA_BF16(acc[mt][nt], ah[mt], bh[nb][i0], bh[nb][i0+1]);\
                    MMA_BF16(acc[mt][nt], ah[mt], bl[nb][i0], bl[nb][i0+1]);\
                    MMA_BF16(acc[mt][nt], al[mt], bh[nb][i0], bh[nb][i0+1]);\
                }                                                          \
        }                                                                  \
    }

__device__ __forceinline__ bool route_setup(int by, int n0,
                                            int& rowblk, int& wlo, int& whi,
                                            bool& useW1) {
    if (by < ROWBLKS) {
        rowblk = by;
        int lo = rowblk * BM, hi2 = lo + BM;
        if (hi2 <= n0)     { useW1 = false; wlo = lo; whi = hi2; }
        else if (lo >= n0) { useW1 = true;  wlo = lo; whi = hi2; }
        else               { useW1 = false; wlo = lo; whi = n0;  }
        return true;
    }
    if ((n0 & (BM - 1)) == 0) return false;
    rowblk = n0 / BM; useW1 = true; wlo = n0; whi = rowblk * BM + BM;
    return true;
}

// =================================================================
// merged QKV GEMM: N=3072; per-CTA segment epilogue
//   cols [0,2048)  -> g_q fp32 (+bq)
//   cols [2048,2560)-> g_k fp32 (+bk)
//   cols [2560,3072)-> g_vh/g_vl bf16 split (+bv)
// =================================================================
__global__ __launch_bounds__(256, 1)
void gemm_qkv(const __nv_bfloat16* __restrict__ Agh,
              const __nv_bfloat16* __restrict__ Agl,
              const float* __restrict__ bq, const float* __restrict__ bqg,
              const float* __restrict__ bk, const float* __restrict__ bkg,
              const float* __restrict__ bv, const float* __restrict__ bvg,
              float* __restrict__ Cq, float* __restrict__ Ck,
              __nv_bfloat16* __restrict__ Vh, __nv_bfloat16* __restrict__ Vl) {
    const int n0 = g_n0;
    int rowblk, wlo, whi;
    bool useW1;
    if (!route_setup(blockIdx.y, n0, rowblk, wlo, whi, useW1)) return;
    const int row0 = rowblk * BM;
    const int col0 = blockIdx.x * BN;

    const __nv_bfloat16* __restrict__ Bh = useW1 ? g_w1h : g_w0h;
    const __nv_bfloat16* __restrict__ Bl = useW1 ? g_w1l : g_w0l;

    GEMM_PROLOGUE_AND_MAINLOOP(Agh, Agl, Bh, Bl)

    // ---- segmented epilogue ----
    const int seg = (col0 < 2048) ? 0 : (col0 < 2560 ? 1 : 2);
    const float* bias;
    int cbase, Nout;
    if (seg == 0)      { bias = useW1 ? bqg : bq; cbase = col0;        Nout = 2048; }
    else if (seg == 1) { bias = useW1 ? bkg : bk; cbase = col0 - 2048; Nout = 512; }
    else               { bias = useW1 ? bvg : bv; cbase = col0 - 2560; Nout = 512; }

#pragma unroll
    for (int mt = 0; mt < 4; mt++) {
        int r0 = row0 + mbase + mt * 16 + (lane >> 2);
        int r1 = r0 + 8;
        bool w0 = (r0 >= wlo) && (r0 < whi);
        bool w1 = (r1 >= wlo) && (r1 < whi);
        int tok0 = w0 ? g_perm[r0] : 0;
        int tok1 = w1 ? g_perm[r1] : 0;
#pragma unroll
        for (int nt = 0; nt < 4; nt++) {
            int colL = cbase + nbase + nt * 8 + (lane & 3) * 2;
            float b0f = bias[colL], b1f = bias[colL + 1];
            float v00 = acc[mt][nt][0] + b0f, v01 = acc[mt][nt][1] + b1f;
            float v10 = acc[mt][nt][2] + b0f, v11 = acc[mt][nt][3] + b1f;
            if (seg < 2) {
                float* C = (seg == 0) ? Cq : Ck;
                if (w0) *(float2*)(C + (size_t)tok0 * Nout + colL) = make_float2(v00, v01);
                if (w1) *(float2*)(C + (size_t)tok1 * Nout + colL) = make_float2(v10, v11);
            } else {
                if (w0) {
                    uint32_t lo_, hi_ = packsplit2(v00, v01, lo_);
                    *(uint32_t*)((uint16_t*)Vh + (size_t)tok0 * 512 + colL) = hi_;
                    *(uint32_t*)((uint16_t*)Vl + (size_t)tok0 * 512 + colL) = lo_;
                }
                if (w1) {
                    uint32_t lo_, hi_ = packsplit2(v10, v11, lo_);
                    *(uint32_t*)((uint16_t*)Vh + (size_t)tok1 * 512 + colL) = hi_;
                    *(uint32_t*)((uint16_t*)Vl + (size_t)tok1 * 512 + colL) = lo_;
                }
            }
        }
    }
}

// =================================================================
// generic routed GEMM (used for O projection, fp32 out, no bias)
// =================================================================
__global__ __launch_bounds__(256, 1)
void gemm_mma(const __nv_bfloat16* __restrict__ Agh,
              const __nv_bfloat16* __restrict__ Agl,
              const __nv_bfloat16* __restrict__ B0h,
              const __nv_bfloat16* __restrict__ B0l,
              const __nv_bfloat16* __restrict__ B1h,
              const __nv_bfloat16* __restrict__ B1l,
              float* __restrict__ C, int N) {
    const int n0 = g_n0;
    int rowblk, wlo, whi;
    bool useW1;
    if (!route_setup(blockIdx.y, n0, rowblk, wlo, whi, useW1)) return;
    const int row0 = rowblk * BM;
    const int col0 = blockIdx.x * BN;

    const __nv_bfloat16* __restrict__ Bh = useW1 ? B1h : B0h;
    const __nv_bfloat16* __restrict__ Bl = useW1 ? B1l : B0l;

    GEMM_PROLOGUE_AND_MAINLOOP(Agh, Agl, Bh, Bl)

#pragma unroll
    for (int mt = 0; mt < 4; mt++) {
        int r0 = row0 + mbase + mt * 16 + (lane >> 2);
        int r1 = r0 + 8;
        bool w0 = (r0 >= wlo) && (r0 < whi);
        bool w1 = (r1 >= wlo) && (r1 < whi);
        int tok0 = w0 ? g_perm[r0] : 0;
        int tok1 = w1 ? g_perm[r1] : 0;
#pragma unroll
        for (int nt = 0; nt < 4; nt++) {
            int colg = col0 + nbase + nt * 8 + (lane & 3) * 2;
            if (w0)
                *(float2*)(C + (size_t)tok0 * N + colg) =
                    make_float2(acc[mt][nt][0], acc[mt][nt][1]);
            if (w1)
                *(float2*)(C + (size_t)tok1 * N + colg) =
                    make_float2(acc[mt][nt][2], acc[mt][nt][3]);
        }
    }
}

// =================================================================
// RMS norm + RoPE; emits bf16 hi/lo (Q pre-scaled by 1/sqrt(D))
// =================================================================
__global__ void rmsrope_kernel(const int* __restrict__ gm,
                               const float* __restrict__ cosb,
                               const float* __restrict__ sinb,
                               const float* __restrict__ qw,
                               const float* __restrict__ qwg,
                               const float* __restrict__ kw,
                               const float* __restrict__ kwg) {
    const int warp = (blockIdx.x * blockDim.x + threadIdx.x) >> 5;
    const int lane = threadIdx.x & 31;
    const int QP = T_TOK * NH;
    if (warp >= QP + T_TOK * NKV) return;
    const float* src;
    __nv_bfloat16 *dh, *dl;
    const float* w;
    int t;
    float oscale;
    if (warp < QP) {
        t = warp >> 4;
        src = g_q + (size_t)warp * HD;
        dh = g_xh + (size_t)warp * HD;
        dl = g_xl + (size_t)warp * HD;
        w = (gm[t] > 0) ? qwg : qw;
        oscale = 0.08838834764831845f;
    } else {
        int p = warp - QP;
        t = p >> 2;
        src = g_k + (size_t)p * HD;
        dh = g_kh + (size_t)p * HD;
        dl = g_kl + (size_t)p * HD;
        w = (gm[t] > 0) ? kwg : kw;
        oscale = 1.0f;
    }
    float v[4];
#pragma unroll
    for (int r = 0; r < 4; r++) v[r] = src[lane + 32 * r];
    float ss = v[0]*v[0] + v[1]*v[1] + v[2]*v[2] + v[3]*v[3];
#pragma unroll
    for (int off = 16; off > 0; off >>= 1)
        ss += __shfl_xor_sync(0xffffffffu, ss, off);
    float rs = rsqrtf(ss * (1.0f / 128.0f) + 1e-6f);
#pragma unroll
    for (int r = 0; r < 4; r++) v[r] = v[r] * rs * w[lane + 32 * r];
    float rot[4] = {-v[2], -v[3], v[0], v[1]};
#pragma unroll
    for (int r = 0; r < 4; r++) {
        int d = lane + 32 * r;
        float c = cosb[(size_t)t * HD + d];
        float s = sinb[(size_t)t * HD + d];
        float val = (v[r] * c + rot[r] * s) * oscale;
        __nv_bfloat16 h = __float2bfloat16(val);
        __nv_bfloat16 l = __float2bfloat16(val - __bfloat162float(h));
        dh[d] = h;
        dl[d] = l;
    }
}

// =================================================================
// FA2 attention, LPT-ordered 1D grid (heaviest q-blocks first)
// =================================================================
#define A_RGN 65536
#define A_SMEM (3 * A_RGN)

__device__ __forceinline__ void load_kv_stage(
    uint32_t rgn, int tid,
    const __nv_bfloat16* __restrict__ kh, const __nv_bfloat16* __restrict__ kl,
    const __nv_bfloat16* __restrict__ vh, const __nv_bfloat16* __restrict__ vl,
    size_t gbase) {
#pragma unroll
    for (int i = 0; i < 4; i++) {
        int idx = tid + (i << 8);
        int row = idx >> 4, c = idx & 15;
        uint32_t d = rgn + row * 256 + ((c ^ (row & 7)) << 4);
        size_t g = gbase + (size_t)row * 512 + c * 8;
        CPA(d,          kh + g);
        CPA(d + 16384,  kl + g);
        CPA(d + 32768,  vh + g);
        CPA(d + 49152,  vl + g);
    }
    CPC();
}

__global__ __launch_bounds__(256, 1)
void attn_mma(const __nv_bfloat16* __restrict__ qh,
              const __nv_bfloat16* __restrict__ ql,
              const __nv_bfloat16* __restrict__ kh,
              const __nv_bfloat16* __restrict__ kl,
              const __nv_bfloat16* __restrict__ vh,
              const __nv_bfloat16* __restrict__ vl,
              float* __restrict__ o) {
    extern __shared__ char smem[];
    const uint32_t sb = smem_to_u32(smem);
    const int tid = threadIdx.x, wid = tid >> 5, lane = tid & 31;
    // LPT: heaviest q-blocks (largest qb) scheduled first
    const int bid = blockIdx.x;
    const int qb = (SEQ / 128 - 1) - (bid >> 7);
    const int hb = bid & 127;
    const int h = hb & 15;
    const int b = hb >> 4;
    const int kvh = h >> 2;
    const int q0 = qb * 128;
    const size_t qgbase = ((size_t)(b * SEQ + q0)) * 2048 + h * 128;
    const size_t kvgbase = ((size_t)(b * SEQ)) * 512 + kvh * 128;
    const int nkb = 2 * qb + 2;

#pragma unroll
    for (int i = 0; i < 8; i++) {
        int idx = tid + (i << 8);
        int row = idx >> 4, c = idx & 15;
        uint32_t d = sb + row * 256 + ((c ^ (row & 7)) << 4);
        size_t g = qgbase + (size_t)row * 2048 + c * 8;
        CPA(d, qh + g);
        CPA(d + 32768, ql + g);
    }
    CPC();
    load_kv_stage(sb + A_RGN, tid, kh, kl, vh, vl, kvgbase);
    CPW(1);
    __syncthreads();

    const int rr = lane & 7;
    const int arow = wid * 16 + ((lane >> 3) & 1) * 8 + rr;
    const int acb = lane >> 4;
    uint32_t Qh[8][4], Ql[8][4];
#pragma unroll
    for (int kk = 0; kk < 8; kk++) {
        int ck = kk * 2 + acb;
        uint32_t ad = sb + arow * 256 + ((ck ^ (arow & 7)) << 4);
        LDSM4(Qh[kk], ad);
        LDSM4(Ql[kk], ad + 32768);
    }
    __syncthreads();
    if (nkb > 1)
        load_kv_stage(sb + 2 * A_RGN, tid, kh, kl, vh, vl, kvgbase + 64 * 512);

    float m0 = -1e30f, m1 = -1e30f, l0 = 0.0f, l1 = 0.0f;
    float oa[16][4];
#pragma unroll
    for (int i = 0; i < 16; i++)
#pragma unroll
        for (int j = 0; j < 4; j++) oa[i][j] = 0.0f;

    const int brow_off = ((lane >> 4) & 1) * 8 + rr;
    const int bcb = (lane >> 3) & 1;
    const int vrow_off = lane & 15;
    const int vcb = lane >> 4;
    const int rowg0 = q0 + wid * 16 + (lane >> 2);
    const int rowg1 = rowg0 + 8;
    const int warprow0 = q0 + wid * 16;

    for (int kb = 0; kb < nkb; kb++) {
        CPW(1);
        __syncthreads();
        if (kb + 2 < nkb)
            load_kv_stage(sb + ((kb + 3) % 3) * A_RGN, tid, kh, kl, vh, vl,
                          kvgbase + (size_t)(kb + 2) * 64 * 512);

        const uint32_t so = sb + ((kb + 1) % 3) * A_RGN;

        float s[8][4];
#pragma unroll
        for (int i = 0; i < 8; i++)
#pragma unroll
            for (int j = 0; j < 4; j++) s[i][j] = 0.0f;

#pragma unroll
        for (int kk = 0; kk < 8; kk++) {
#pragma unroll
            for (int p = 0; p < 4; p++) {
                int krow = p * 16 + brow_off;
                int ck = kk * 2 + bcb;
                uint32_t kd = so + krow * 256 + ((ck ^ (krow & 7)) << 4);
                uint32_t bh4[4], bl4[4];
                LDSM4(bh4, kd);
                LDSM4(bl4, kd + 16384);
                MMA_BF16(s[2*p],   Qh[kk], bh4[0], bh4[1]);
                MMA_BF16(s[2*p],   Qh[kk], bl4[0], bl4[1]);
                MMA_BF16(s[2*p],   Ql[kk], bh4[0], bh4[1]);
                MMA_BF16(s[2*p+1], Qh[kk], bh4[2], bh4[3]);
                MMA_BF16(s[2*p+1], Qh[kk], bl4[2], bl4[3]);
                MMA_BF16(s[2*p+1], Ql[kk], bh4[2], bh4[3]);
            }
        }

        if (kb * 64 + 63 > warprow0) {
            int colb = kb * 64 + (lane & 3) * 2;
#pragma unroll
            for (int nt = 0; nt < 8; nt++) {
                int c = colb + nt * 8;
                if (c > rowg0)     s[nt][0] = -1e30f;
                if (c + 1 > rowg0) s[nt][1] = -1e30f;
                if (c > rowg1)     s[nt][2] = -1e30f;
                if (c + 1 > rowg1) s[nt][3] = -1e30f;
            }
        }

        float mx0 = -1e30f, mx1 = -1e30f;
#pragma unroll
        for (int nt = 0; nt < 8; nt++) {
            mx0 = fmaxf(mx0, fmaxf(s[nt][0], s[nt][1]));
            mx1 = fmaxf(mx1, fmaxf(s[nt][2], s[nt][3]));
        }
        mx0 = fmaxf(mx0, __shfl_xor_sync(0xffffffffu, mx0, 1));
        mx0 = fmaxf(mx0, __shfl_xor_sync(0xffffffffu, mx0, 2));
        mx1 = fmaxf(mx1, __shfl_xor_sync(0xffffffffu, mx1, 1));
        mx1 = fmaxf(mx1, __shfl_xor_sync(0xffffffffu, mx1, 2));
        float nm0 = fmaxf(m0, mx0), nm1 = fmaxf(m1, mx1);
        float corr0 = __expf(m0 - nm0), corr1 = __expf(m1 - nm1);
        float ps0 = 0.0f, ps1 = 0.0f;
#pragma unroll
        for (int nt = 0; nt < 8; nt++) {
            s[nt][0] = __expf(s[nt][0] - nm0);
            s[nt][1] = __expf(s[nt][1] - nm0);
            s[nt][2] = __expf(s[nt][2] - nm1);
            s[nt][3] = __expf(s[nt][3] - nm1);
            ps0 += s[nt][0] + s[nt][1];
            ps1 += s[nt][2] + s[nt][3];
        }
        ps0 += __shfl_xor_sync(0xffffffffu, ps0, 1);
        ps0 += __shfl_xor_sync(0xffffffffu, ps0, 2);
        ps1 += __shfl_xor_sync(0xffffffffu, ps1, 1);
        ps1 += __shfl_xor_sync(0xffffffffu, ps1, 2);
        l0 = l0 * corr0 + ps0;
        l1 = l1 * corr1 + ps1;
        m0 = nm0; m1 = nm1;
#pragma unroll
        for (int i = 0; i < 16; i++) {
            oa[i][0] *= corr0; oa[i][1] *= corr0;
            oa[i][2] *= corr1; oa[i][3] *= corr1;
        }

#pragma unroll
        for (int kt = 0; kt < 4; kt++) {
            uint32_t ah4[4], al4[4];
            ah4[0] = packsplit2(s[2*kt][0],   s[2*kt][1],   al4[0]);
            ah4[1] = packsplit2(s[2*kt][2],   s[2*kt][3],   al4[1]);
            ah4[2] = packsplit2(s[2*kt+1][0], s[2*kt+1][1], al4[2]);
            ah4[3] = packsplit2(s[2*kt+1][2], s[2*kt+1][3], al4[3]);
#pragma unroll
            for (int dp = 0; dp < 8; dp++) {
                int vr = kt * 16 + vrow_off;
                int ck = dp * 2 + vcb;
                uint32_t vd = so + 32768 + vr * 256 + ((ck ^ (vr & 7)) << 4);
                uint32_t bh4[4], bl4[4];
                LDSM4T(bh4, vd);
                LDSM4T(bl4, vd + 16384);
                MMA_BF16(oa[2*dp],   ah4, bh4[0], bh4[1]);
                MMA_BF16(oa[2*dp],   ah4, bl4[0], bl4[1]);
                MMA_BF16(oa[2*dp],   al4, bh4[0], bh4[1]);
                MMA_BF16(oa[2*dp+1], ah4, bh4[2], bh4[3]);
                MMA_BF16(oa[2*dp+1], ah4, bl4[2], bl4[3]);
                MMA_BF16(oa[2*dp+1], al4, bh4[2], bh4[3]);
            }
        }
    }

    float inv0 = 1.0f / l0, inv1 = 1.0f / l1;
    size_t ob0 = ((size_t)(b * SEQ + rowg0)) * 2048 + h * 128 + (lane & 3) * 2;
    size_t ob1 = ((size_t)(b * SEQ + rowg1)) * 2048 + h * 128 + (lane & 3) * 2;
#pragma unroll
    for (int nt = 0; nt < 16; nt++) {
        float2 v0 = {oa[nt][0] * inv0, oa[nt][1] * inv0};
        float2 v1 = {oa[nt][2] * inv1, oa[nt][3] * inv1};
        *(float2*)(o + ob0 + nt * 8) = v0;
        *(float2*)(o + ob1 + nt * 8) = v1;
    }
}

// -------- launch --------
extern "C" void kernel_launch(void* const* d_in, const int* in_sizes, int n_in,
                              void* d_out, int out_size) {
    const float* x    = (const float*)d_in[0];
    const float* cosb = (const float*)d_in[1];
    const float* sinb = (const float*)d_in[2];
    const int*   gm   = (const int*)d_in[4];
    const float* Wq   = (const float*)d_in[5];
    const float* bq   = (const float*)d_in[6];
    const float* Wqg  = (const float*)d_in[7];
    const float* bqg  = (const float*)d_in[8];
    const float* Wk   = (const float*)d_in[9];
    const float* bk   = (const float*)d_in[10];
    const float* Wkg  = (const float*)d_in[11];
    const float* bkg  = (const float*)d_in[12];
    const float* Wv   = (const float*)d_in[13];
    const float* bv   = (const float*)d_in[14];
    const float* Wvg  = (const float*)d_in[15];
    const float* bvg  = (const float*)d_in[16];
    const float* Wo   = (const float*)d_in[17];
    const float* Wog  = (const float*)d_in[18];
    const float* qw   = (const float*)d_in[19];
    const float* qwg  = (const float*)d_in[20];
    const float* kw   = (const float*)d_in[21];
    const float* kwg  = (const float*)d_in[22];
    float* out = (float*)d_out;

    void *pq, *pk, *po, *pxh, *pxl, *pkh, *pkl, *pvh, *pvl;
    cudaGetSymbolAddress(&pq, g_q);
    cudaGetSymbolAddress(&pk, g_k);
    cudaGetSymbolAddress(&po, g_o);
    cudaGetSymbolAddress(&pxh, g_xh);
    cudaGetSymbolAddress(&pxl, g_xl);
    cudaGetSymbolAddress(&pkh, g_kh);
    cudaGetSymbolAddress(&pkl, g_kl);
    cudaGetSymbolAddress(&pvh, g_vh);
    cudaGetSymbolAddress(&pvl, g_vl);
    float *qbuf = (float*)pq, *kbuf = (float*)pk, *obuf = (float*)po;
    __nv_bfloat16 *xh = (__nv_bfloat16*)pxh, *xl = (__nv_bfloat16*)pxl;

    void *w0h, *w0l, *w1h, *w1l, *woh, *wol, *wogh, *wogl;
    cudaGetSymbolAddress(&w0h, g_w0h);   cudaGetSymbolAddress(&w0l, g_w0l);
    cudaGetSymbolAddress(&w1h, g_w1h);   cudaGetSymbolAddress(&w1l, g_w1l);
    cudaGetSymbolAddress(&woh, g_woh);   cudaGetSymbolAddress(&wol, g_wol);
    cudaGetSymbolAddress(&wogh, g_wogh); cudaGetSymbolAddress(&wogl, g_wogl);

    cudaFuncSetAttribute(gemm_qkv, cudaFuncAttributeMaxDynamicSharedMemorySize,
                         GSMEM);
    cudaFuncSetAttribute(gemm_mma, cudaFuncAttributeMaxDynamicSharedMemorySize,
                         GSMEM);
    cudaFuncSetAttribute(attn_mma, cudaFuncAttributeMaxDynamicSharedMemorySize,
                         A_SMEM);

    partition_kernel<<<1, 1024>>>(gm);

    cvt_perm<<<T_TOK * 512 / 256, 256>>>(x, xh, xl);
    cvt_qkvw<<<NQKV * 512 / 256, 256>>>(Wq, Wk, Wv,
                                        (__nv_bfloat16*)w0h, (__nv_bfloat16*)w0l);
    cvt_qkvw<<<NQKV * 512 / 256, 256>>>(Wqg, Wkg, Wvg,
                                        (__nv_bfloat16*)w1h, (__nv_bfloat16*)w1l);
    const int NB_BIG = 2048 * 2048 / 4 / 256;
    cvt_plain<<<NB_BIG, 256>>>(Wo,  (__nv_bfloat16*)woh,  (__nv_bfloat16*)wol);
    cvt_plain<<<NB_BIG, 256>>>(Wog, (__nv_bfloat16*)wogh, (__nv_bfloat16*)wogl);

    // merged QKV projection
    gemm_qkv<<<dim3(NQKV / BN, ROWBLKS + 1), 256, GSMEM>>>(
        xh, xl, bq, bqg, bk, bkg, bv, bvg,
        qbuf, kbuf, (__nv_bfloat16*)pvh, (__nv_bfloat16*)pvl);

    {
        int warps = T_TOK * (NH + NKV);
        rmsrope_kernel<<<(warps * 32 + 255) / 256, 256>>>(gm, cosb, sinb,
                                                          qw, qwg, kw, kwg);
    }

    attn_mma<<<(SEQ / 128) * NH * BATCH, 256, A_SMEM>>>(
        xh, xl, (__nv_bfloat16*)pkh, (__nv_bfloat16*)pkl,
        (__nv_bfloat16*)pvh, (__nv_bfloat16*)pvl, obuf);

    cvt_perm<<<T_TOK * 512 / 256, 256>>>(obuf, xh, xl);
    gemm_mma<<<dim3(HIDDEN / BN, ROWBLKS + 1), 256, GSMEM>>>(
        xh, xl, (__nv_bfloat16*)woh, (__nv_bfloat16*)wol,
        (__nv_bfloat16*)wogh, (__nv_bfloat16*)wogl, out, HIDDEN);
}